// round 2
// baseline (speedup 1.0000x reference)
#include <cuda_runtime.h>

// Problem constants
#define BATCH   2
#define T_SEQ   2048
#define DMODEL  1024
#define NHEAD   16
#define HD      64
#define FFDIM   4096
#define BT      (BATCH*T_SEQ)          // 4096 rows

// ---------------------------------------------------------------------------
// Scratch (static __device__ globals; no allocation anywhere)
// ---------------------------------------------------------------------------
__device__ float g_Wqkv[(size_t)DMODEL * 3 * DMODEL];                 // 1024 x 3072
__device__ float g_qkv[(size_t)BT * 3 * DMODEL];                      // 4096 x 3072
__device__ float g_scores[(size_t)BATCH * NHEAD * T_SEQ * T_SEQ];     // 32 x 2048 x 2048
__device__ float g_obuf[(size_t)BT * DMODEL];
__device__ float g_proj[(size_t)BT * DMODEL];
__device__ float g_out1[(size_t)BT * DMODEL];
__device__ float g_h1[(size_t)BT * FFDIM];
__device__ float g_ff[(size_t)BT * DMODEL];

// ---------------------------------------------------------------------------
// Pack Wq|Wk|Wv (each H x D x 64, h-major) into Wqkv[d][n], n = which*1024 + h*64 + k
// ---------------------------------------------------------------------------
__global__ void pack_w_kernel(const float* __restrict__ Wq,
                              const float* __restrict__ Wk,
                              const float* __restrict__ Wv,
                              float* __restrict__ Wqkv) {
    int idx = blockIdx.x * blockDim.x + threadIdx.x;   // over 1024*3072
    int d = idx / (3 * DMODEL);
    int n = idx % (3 * DMODEL);
    const float* W = (n < DMODEL) ? Wq : ((n < 2 * DMODEL) ? Wk : Wv);
    int nn = n & (DMODEL - 1);
    int h = nn >> 6;
    int k = nn & 63;
    Wqkv[idx] = W[((size_t)h * DMODEL + d) * HD + k];
}

// ---------------------------------------------------------------------------
// Generic tiled SGEMM.
// C[M,N] = alpha * A[M,K] x B  (+bias) (+relu)
//   TRANSB=false: B is K x N row-major (ldb)
//   TRANSB=true : B is N x K row-major (ldb)  (i.e. C = alpha * A * B^T)
// Batched via blockIdx.z: z1 = z / zInner, z2 = z % zInner;
//   each operand offset by z1*s?1 + z2*s?2 (element strides).
// All of M,N multiples of BM,BN; K multiple of BK; pointers float4-aligned.
// ---------------------------------------------------------------------------
template<int BM, int BN, int BK, int TM, int TN, bool TRANSB, bool RELU, bool HASBIAS>
__global__ void __launch_bounds__((BM/TM)*(BN/TN))
sgemm_kernel(const float* __restrict__ Ag, const float* __restrict__ Bg,
             float* __restrict__ Cg, const float* __restrict__ bias,
             int M, int N, int K, int lda, int ldb, int ldc,
             long long sA1, long long sA2,
             long long sB1, long long sB2,
             long long sC1, long long sC2,
             int zInner, float alpha)
{
    constexpr int NTH = (BM/TM)*(BN/TN);
    const int z1 = blockIdx.z / zInner;
    const int z2 = blockIdx.z % zInner;
    const float* A = Ag + z1 * sA1 + z2 * sA2;
    const float* B = Bg + z1 * sB1 + z2 * sB2;
    float*       C = Cg + z1 * sC1 + z2 * sC2;

    __shared__ __align__(16) float As[BK][BM + 4];
    __shared__ __align__(16) float Bs[BK][BN + 4];

    const int tid  = threadIdx.x;
    const int row0 = blockIdx.y * BM;
    const int col0 = blockIdx.x * BN;
    const int tcol = tid % (BN/TN);
    const int trow = tid / (BN/TN);

    float acc[TM][TN];
    #pragma unroll
    for (int i = 0; i < TM; i++)
        #pragma unroll
        for (int j = 0; j < TN; j++) acc[i][j] = 0.f;

    for (int k0 = 0; k0 < K; k0 += BK) {
        // load A tile (BM x BK), store transposed into As[k][m]
        #pragma unroll
        for (int i = tid; i < BM * (BK/4); i += NTH) {
            int r  = i / (BK/4);
            int c4 = (i % (BK/4)) * 4;
            float4 v = *reinterpret_cast<const float4*>(
                A + (size_t)(row0 + r) * lda + k0 + c4);
            As[c4+0][r] = v.x; As[c4+1][r] = v.y;
            As[c4+2][r] = v.z; As[c4+3][r] = v.w;
        }
        if (TRANSB) {
            // B is N x K: load BN x BK, store transposed into Bs[k][n]
            #pragma unroll
            for (int i = tid; i < BN * (BK/4); i += NTH) {
                int r  = i / (BK/4);
                int c4 = (i % (BK/4)) * 4;
                float4 v = *reinterpret_cast<const float4*>(
                    B + (size_t)(col0 + r) * ldb + k0 + c4);
                Bs[c4+0][r] = v.x; Bs[c4+1][r] = v.y;
                Bs[c4+2][r] = v.z; Bs[c4+3][r] = v.w;
            }
        } else {
            // B is K x N: load BK x BN directly
            #pragma unroll
            for (int i = tid; i < BK * (BN/4); i += NTH) {
                int r  = i / (BN/4);
                int c4 = (i % (BN/4)) * 4;
                float4 v = *reinterpret_cast<const float4*>(
                    B + (size_t)(k0 + r) * ldb + col0 + c4);
                *reinterpret_cast<float4*>(&Bs[r][c4]) = v;
            }
        }
        __syncthreads();

        #pragma unroll
        for (int kk = 0; kk < BK; kk++) {
            float ra[TM], rb[TN];
            #pragma unroll
            for (int i = 0; i < TM; i += 4) {
                float4 t = *reinterpret_cast<const float4*>(&As[kk][trow*TM + i]);
                ra[i+0] = t.x; ra[i+1] = t.y; ra[i+2] = t.z; ra[i+3] = t.w;
            }
            #pragma unroll
            for (int j = 0; j < TN; j += 4) {
                float4 t = *reinterpret_cast<const float4*>(&Bs[kk][tcol*TN + j]);
                rb[j+0] = t.x; rb[j+1] = t.y; rb[j+2] = t.z; rb[j+3] = t.w;
            }
            #pragma unroll
            for (int i = 0; i < TM; i++)
                #pragma unroll
                for (int j = 0; j < TN; j++)
                    acc[i][j] = fmaf(ra[i], rb[j], acc[i][j]);
        }
        __syncthreads();
    }

    // epilogue
    #pragma unroll
    for (int i = 0; i < TM; i++) {
        size_t r = (size_t)(row0 + trow * TM + i);
        #pragma unroll
        for (int j = 0; j < TN; j += 4) {
            int c = col0 + tcol * TN + j;
            float4 v;
            v.x = acc[i][j+0] * alpha;
            v.y = acc[i][j+1] * alpha;
            v.z = acc[i][j+2] * alpha;
            v.w = acc[i][j+3] * alpha;
            if (HASBIAS) {
                float4 bb = *reinterpret_cast<const float4*>(bias + c);
                v.x += bb.x; v.y += bb.y; v.z += bb.z; v.w += bb.w;
            }
            if (RELU) {
                v.x = fmaxf(v.x, 0.f); v.y = fmaxf(v.y, 0.f);
                v.z = fmaxf(v.z, 0.f); v.w = fmaxf(v.w, 0.f);
            }
            *reinterpret_cast<float4*>(C + r * ldc + c) = v;
        }
    }
}

// ---------------------------------------------------------------------------
// Column softmax over the QUERY axis: scores[bh][q][s] normalized over q.
// One thread per column s; strided reads are coalesced across threads.
// ---------------------------------------------------------------------------
__global__ void softmax_q_kernel(float* __restrict__ sc) {
    int s = blockIdx.x * blockDim.x + threadIdx.x;          // column
    float* base = sc + (size_t)blockIdx.y * T_SEQ * T_SEQ + s;
    float m = -1e30f, sum = 0.f;
    for (int q = 0; q < T_SEQ; q++) {
        float x  = base[(size_t)q * T_SEQ];
        float mn = fmaxf(m, x);
        sum = sum * __expf(m - mn) + __expf(x - mn);
        m = mn;
    }
    float r = 1.f / sum;
    for (int q = 0; q < T_SEQ; q++) {
        float x = base[(size_t)q * T_SEQ];
        base[(size_t)q * T_SEQ] = __expf(x - m) * r;
    }
}

// ---------------------------------------------------------------------------
// out = meanstd_norm(A + B), per row of DMODEL, ddof=1 (÷1023), no eps.
// One block (256 threads) per row.
// ---------------------------------------------------------------------------
__device__ __forceinline__ float block_reduce_sum(float v, float* sh) {
    int lane = threadIdx.x & 31, warp = threadIdx.x >> 5;
    #pragma unroll
    for (int o = 16; o; o >>= 1) v += __shfl_xor_sync(0xffffffffu, v, o);
    if (lane == 0) sh[warp] = v;
    __syncthreads();
    if (warp == 0) {
        v = (lane < 8) ? sh[lane] : 0.f;
        #pragma unroll
        for (int o = 16; o; o >>= 1) v += __shfl_xor_sync(0xffffffffu, v, o);
        if (lane == 0) sh[0] = v;
    }
    __syncthreads();
    float r = sh[0];
    __syncthreads();            // allow sh reuse
    return r;
}

__global__ void add_norm_kernel(const float* __restrict__ A,
                                const float* __restrict__ B,
                                float* __restrict__ out) {
    __shared__ float sh[32];
    size_t row = blockIdx.x;
    const float* pa = A + row * DMODEL;
    const float* pb = B + row * DMODEL;
    float* po = out + row * DMODEL;

    float v[4];
    float s = 0.f;
    #pragma unroll
    for (int i = 0; i < 4; i++) {
        int c = threadIdx.x + i * 256;
        v[i] = pa[c] + pb[c];
        s += v[i];
    }
    float total = block_reduce_sum(s, sh);
    float mean = total * (1.f / (float)DMODEL);

    float ss = 0.f;
    #pragma unroll
    for (int i = 0; i < 4; i++) {
        float d = v[i] - mean;
        ss += d * d;
    }
    float tss = block_reduce_sum(ss, sh);
    float rstd = rsqrtf(tss * (1.f / (float)(DMODEL - 1)));

    #pragma unroll
    for (int i = 0; i < 4; i++) {
        int c = threadIdx.x + i * 256;
        po[c] = (v[i] - mean) * rstd;
    }
}

// ---------------------------------------------------------------------------
// Launch
// ---------------------------------------------------------------------------
extern "C" void kernel_launch(void* const* d_in, const int* in_sizes, int n_in,
                              void* d_out, int out_size) {
    const float* x  = (const float*)d_in[0];
    const float* Wq = (const float*)d_in[1];
    const float* Wk = (const float*)d_in[2];
    const float* Wv = (const float*)d_in[3];
    const float* Wo = (const float*)d_in[4];
    const float* W1 = (const float*)d_in[5];
    const float* b1 = (const float*)d_in[6];
    const float* W2 = (const float*)d_in[7];
    const float* b2 = (const float*)d_in[8];
    float* out = (float*)d_out;

    float *Wqkv, *qkv, *scores, *obuf, *proj, *out1, *h1, *ff;
    cudaGetSymbolAddress((void**)&Wqkv,   g_Wqkv);
    cudaGetSymbolAddress((void**)&qkv,    g_qkv);
    cudaGetSymbolAddress((void**)&scores, g_scores);
    cudaGetSymbolAddress((void**)&obuf,   g_obuf);
    cudaGetSymbolAddress((void**)&proj,   g_proj);
    cudaGetSymbolAddress((void**)&out1,   g_out1);
    cudaGetSymbolAddress((void**)&h1,     g_h1);
    cudaGetSymbolAddress((void**)&ff,     g_ff);

    const long long TT = (long long)T_SEQ * T_SEQ;

    // 1) pack Wq|Wk|Wv -> Wqkv (1024 x 3072)
    pack_w_kernel<<<(DMODEL * 3 * DMODEL) / 256, 256>>>(Wq, Wk, Wv, Wqkv);

    // 2) QKV = X(4096x1024) @ Wqkv(1024x3072)
    sgemm_kernel<128,128,16,8,8,false,false,false>
        <<<dim3(3*DMODEL/128, BT/128, 1), 256>>>(
            x, Wqkv, qkv, nullptr,
            BT, 3*DMODEL, DMODEL, DMODEL, 3*DMODEL, 3*DMODEL,
            0,0, 0,0, 0,0, 1, 1.0f);

    // 3) scores[b,h] = (Q @ K^T) / 8 ; batched over z=(b,h), zInner=NHEAD
    sgemm_kernel<128,128,16,8,8,true,false,false>
        <<<dim3(T_SEQ/128, T_SEQ/128, BATCH*NHEAD), 256>>>(
            qkv /*Q*/, qkv + DMODEL /*K*/, scores, nullptr,
            T_SEQ, T_SEQ, HD, 3*DMODEL, 3*DMODEL, T_SEQ,
            (long long)T_SEQ*3*DMODEL, HD,
            (long long)T_SEQ*3*DMODEL, HD,
            (long long)NHEAD*TT, TT,
            NHEAD, 0.125f);

    // 4) softmax over query axis (columns)
    softmax_q_kernel<<<dim3(T_SEQ/256, BATCH*NHEAD), 256>>>(scores);

    // 5) O[b,h] = attn(2048x2048) @ V(2048x64) -> obuf[b,t,h*64+v]
    sgemm_kernel<128,64,16,8,4,false,false,false>
        <<<dim3(1, T_SEQ/128, BATCH*NHEAD), 256>>>(
            scores, qkv + 2*DMODEL /*V*/, obuf, nullptr,
            T_SEQ, HD, T_SEQ, T_SEQ, 3*DMODEL, DMODEL,
            (long long)NHEAD*TT, TT,
            (long long)T_SEQ*3*DMODEL, HD,
            (long long)T_SEQ*DMODEL, HD,
            NHEAD, 1.0f);

    // 6) proj = obuf(4096x1024) @ Wo(1024x1024)
    sgemm_kernel<128,128,16,8,8,false,false,false>
        <<<dim3(DMODEL/128, BT/128, 1), 256>>>(
            obuf, Wo, proj, nullptr,
            BT, DMODEL, DMODEL, DMODEL, DMODEL, DMODEL,
            0,0, 0,0, 0,0, 1, 1.0f);

    // 7) out1 = norm(proj + x)
    add_norm_kernel<<<BT, 256>>>(proj, x, out1);

    // 8) h1 = relu(out1 @ W1 + b1)   (4096x4096)
    sgemm_kernel<128,128,16,8,8,false,true,true>
        <<<dim3(FFDIM/128, BT/128, 1), 256>>>(
            out1, W1, h1, b1,
            BT, FFDIM, DMODEL, DMODEL, FFDIM, FFDIM,
            0,0, 0,0, 0,0, 1, 1.0f);

    // 9) ff = h1 @ W2 + b2           (4096x1024)
    sgemm_kernel<128,128,16,8,8,false,false,true>
        <<<dim3(DMODEL/128, BT/128, 1), 256>>>(
            h1, W2, ff, b2,
            BT, DMODEL, FFDIM, FFDIM, DMODEL, DMODEL,
            0,0, 0,0, 0,0, 1, 1.0f);

    // 10) out = norm(ff + out1)
    add_norm_kernel<<<BT, 256>>>(ff, out1, out);
}

// round 5
// speedup vs baseline: 2.2443x; 2.2443x over previous
#include <cuda_runtime.h>
#include <cuda_bf16.h>
#include <cstdint>
typedef __nv_bfloat16 bf16;

#define BATCH 2
#define TS 2048
#define DM 1024
#define NH 16
#define HD 64
#define FFD 4096
#define BT (BATCH*TS)
#define NBH (BATCH*NH)

// ---------------- scratch (fp32 everywhere; no allocation) ----------------
__device__ float g_WqkvT[(size_t)3*DM*DM];   // [3072][1024]
__device__ float g_WoT[(size_t)DM*DM];       // [1024][1024]
__device__ float g_W1T[(size_t)FFD*DM];      // [4096][1024]
__device__ float g_W2T[(size_t)DM*FFD];      // [1024][4096]
__device__ float g_qkv[(size_t)BT*3*DM];
__device__ float g_scores[(size_t)NBH*TS*TS];  // exp(QK^T/8)
__device__ float g_Zpart[(size_t)NBH*16*TS];
__device__ float g_Zr[(size_t)NBH*TS];
__device__ float g_vt[(size_t)NBH*HD*TS];      // V^T/Z  [bh][v][s]
__device__ float g_obuf[(size_t)BT*DM];
__device__ float g_proj[(size_t)BT*DM];
__device__ float g_out1[(size_t)BT*DM];
__device__ float g_h1[(size_t)BT*FFD];
__device__ float g_ff[(size_t)BT*DM];

// ---------------- helpers ----------------
__device__ __forceinline__ uint32_t smem_u32(const void* p) {
    uint32_t a;
    asm("{ .reg .u64 t; cvta.to.shared.u64 t, %1; cvt.u32.u64 %0, t; }" : "=r"(a) : "l"(p));
    return a;
}
__device__ __forceinline__ void ldsm4(uint32_t (&r)[4], uint32_t addr) {
    asm volatile("ldmatrix.sync.aligned.m8n8.x4.shared.b16 {%0,%1,%2,%3}, [%4];"
        : "=r"(r[0]), "=r"(r[1]), "=r"(r[2]), "=r"(r[3]) : "r"(addr));
}
__device__ __forceinline__ void mma16816(float (&d)[4], const uint32_t (&a)[4],
                                         const uint32_t* b) {
    asm volatile("mma.sync.aligned.m16n8k16.row.col.f32.bf16.bf16.f32 "
        "{%0,%1,%2,%3}, {%4,%5,%6,%7}, {%8,%9}, {%0,%1,%2,%3};"
        : "+f"(d[0]), "+f"(d[1]), "+f"(d[2]), "+f"(d[3])
        : "r"(a[0]), "r"(a[1]), "r"(a[2]), "r"(a[3]), "r"(b[0]), "r"(b[1]));
}
__device__ __forceinline__ uint32_t pack2(bf16 a, bf16 b) {
    __nv_bfloat162 t; t.x = a; t.y = b;
    return *reinterpret_cast<uint32_t*>(&t);
}
__device__ __forceinline__ void cvt2(float a, float b, uint32_t& hi, uint32_t& lo) {
    bf16 h0 = __float2bfloat16(a), h1 = __float2bfloat16(b);
    hi = pack2(h0, h1);
    lo = pack2(__float2bfloat16(a - __bfloat162float(h0)),
               __float2bfloat16(b - __bfloat162float(h1)));
}

// ---------------- split-bf16 mma.sync GEMM: C = f(alpha * A @ B^T) ----------------
// A fp32 [M][K] (lda), B fp32 [N][K] (ldb); EPI: 0 plain, 1 exp(alpha*x)+Zpart, 2 bias, 3 bias+relu
template<int BN, int EPI>
__global__ void __launch_bounds__(256, 1)
mma_gemm(const float* __restrict__ Af, const float* __restrict__ Bf,
         float* __restrict__ Cf, const float* __restrict__ bias,
         float* __restrict__ Zpart,
         int K, int lda, int ldb, int ldc,
         long long sA1, long long sA2, long long sB1, long long sB2,
         long long sC1, long long sC2, int zInner, float alpha)
{
    constexpr int BM = 128, WC = 2, WN = BN/WC, NF = WN/8;
    constexpr int LDT = 40;                     // bf16 elems per smem row (80B: conflict-free)
    constexpr int ASZ = BM*LDT, BSZ = BN*LDT;   // bf16 elems per plane
    constexpr int STG = 2*ASZ + 2*BSZ;          // Ah,Al,Bh,Bl
    constexpr int NA4 = BM*8/256, NB4 = BN*8/256;

    extern __shared__ char dsm[];
    bf16* smem = (bf16*)dsm;
    float* sZ = (float*)(dsm + (size_t)2*STG*2);
    const uint32_t sbase = smem_u32(dsm);

    const int tid = threadIdx.x, wid = tid >> 5, lane = tid & 31;
    const int wr = wid & 3, wc = wid >> 2, g = lane >> 2, tig = lane & 3;
    const int z = blockIdx.z, z1 = z / zInner, z2 = z % zInner;
    const int row0 = blockIdx.y * BM, col0 = blockIdx.x * BN;
    const float* pA = Af + z1*sA1 + z2*sA2 + (size_t)row0*lda;
    const float* pB = Bf + z1*sB1 + z2*sB2 + (size_t)col0*ldb;

    float acc[2][NF][4];
    #pragma unroll
    for (int mf = 0; mf < 2; mf++)
        #pragma unroll
        for (int nf = 0; nf < NF; nf++)
            #pragma unroll
            for (int q = 0; q < 4; q++) acc[mf][nf][q] = 0.f;

    float4 rA[NA4], rB[NB4];
    const int NC = K >> 5;

    auto loadG = [&](int c) {
        #pragma unroll
        for (int i = 0; i < NA4; i++) {
            int idx = tid + i*256, r = idx >> 3, kq = idx & 7;
            rA[i] = __ldg((const float4*)(pA + (size_t)r*lda + c*32 + kq*4));
        }
        #pragma unroll
        for (int i = 0; i < NB4; i++) {
            int idx = tid + i*256, r = idx >> 3, kq = idx & 7;
            rB[i] = __ldg((const float4*)(pB + (size_t)r*ldb + c*32 + kq*4));
        }
    };
    auto stsC = [&](int buf) {
        bf16* ah = smem + (size_t)buf*STG;
        bf16* al = ah + ASZ; bf16* bh = al + ASZ; bf16* bl = bh + BSZ;
        #pragma unroll
        for (int i = 0; i < NA4; i++) {
            int idx = tid + i*256, r = idx >> 3, kq = idx & 7, off = r*LDT + kq*4;
            uint32_t h0, l0, h1, l1;
            cvt2(rA[i].x, rA[i].y, h0, l0); cvt2(rA[i].z, rA[i].w, h1, l1);
            uint2 u; u.x = h0; u.y = h1; *reinterpret_cast<uint2*>(ah + off) = u;
            u.x = l0; u.y = l1;           *reinterpret_cast<uint2*>(al + off) = u;
        }
        #pragma unroll
        for (int i = 0; i < NB4; i++) {
            int idx = tid + i*256, r = idx >> 3, kq = idx & 7, off = r*LDT + kq*4;
            uint32_t h0, l0, h1, l1;
            cvt2(rB[i].x, rB[i].y, h0, l0); cvt2(rB[i].z, rB[i].w, h1, l1);
            uint2 u; u.x = h0; u.y = h1; *reinterpret_cast<uint2*>(bh + off) = u;
            u.x = l0; u.y = l1;           *reinterpret_cast<uint2*>(bl + off) = u;
        }
    };
    auto comp = [&](int buf) {
        const uint32_t aB  = sbase + (uint32_t)buf*STG*2;
        const uint32_t alB = aB + ASZ*2, bB = alB + ASZ*2, blB = bB + BSZ*2;
        #pragma unroll
        for (int ks = 0; ks < 2; ks++) {
            uint32_t ah[2][4], al[2][4], bh[NF][2], bl[NF][2];
            #pragma unroll
            for (int mf = 0; mf < 2; mf++) {
                int row = wr*32 + mf*16 + (lane & 15);
                int kc  = ks*16 + ((lane >> 4) << 3);
                uint32_t off = (uint32_t)(row*LDT + kc)*2;
                ldsm4(ah[mf], aB + off);
                ldsm4(al[mf], alB + off);
            }
            #pragma unroll
            for (int nq = 0; nq < NF/2; nq++) {
                int n  = wc*WN + nq*16 + (lane & 7) + ((lane >> 4) << 3);
                int kc = ks*16 + (((lane >> 3) & 1) << 3);
                uint32_t off = (uint32_t)(n*LDT + kc)*2, t[4];
                ldsm4(t, bB + off);
                bh[2*nq][0]=t[0]; bh[2*nq][1]=t[1]; bh[2*nq+1][0]=t[2]; bh[2*nq+1][1]=t[3];
                ldsm4(t, blB + off);
                bl[2*nq][0]=t[0]; bl[2*nq][1]=t[1]; bl[2*nq+1][0]=t[2]; bl[2*nq+1][1]=t[3];
            }
            #pragma unroll
            for (int mf = 0; mf < 2; mf++)
                #pragma unroll
                for (int nf = 0; nf < NF; nf++) {
                    mma16816(acc[mf][nf], ah[mf], bh[nf]);
                    mma16816(acc[mf][nf], ah[mf], bl[nf]);
                    mma16816(acc[mf][nf], al[mf], bh[nf]);
                }
        }
    };

    loadG(0); stsC(0);
    for (int c = 0; c < NC; c++) {
        __syncthreads();
        if (c + 1 < NC) loadG(c + 1);
        comp(c & 1);
        if (c + 1 < NC) { __syncthreads(); stsC((c + 1) & 1); }
    }

    // ---- epilogue ----
    float* pC = Cf + z1*sC1 + z2*sC2;
    float cs[NF][2];
    if (EPI == 1)
        #pragma unroll
        for (int nf = 0; nf < NF; nf++) { cs[nf][0] = 0.f; cs[nf][1] = 0.f; }

    #pragma unroll
    for (int mf = 0; mf < 2; mf++) {
        int rg = row0 + wr*32 + mf*16 + g;
        #pragma unroll
        for (int nf = 0; nf < NF; nf++) {
            int col = col0 + wc*WN + nf*8 + tig*2;
            float v0 = acc[mf][nf][0], v1 = acc[mf][nf][1];
            float v2 = acc[mf][nf][2], v3 = acc[mf][nf][3];
            if (EPI >= 2) {
                float b0 = __ldg(bias + col), b1 = __ldg(bias + col + 1);
                v0 += b0; v1 += b1; v2 += b0; v3 += b1;
            }
            if (EPI == 3) {
                v0 = fmaxf(v0, 0.f); v1 = fmaxf(v1, 0.f);
                v2 = fmaxf(v2, 0.f); v3 = fmaxf(v3, 0.f);
            }
            if (EPI == 1) {
                v0 = __expf(v0*alpha); v1 = __expf(v1*alpha);
                v2 = __expf(v2*alpha); v3 = __expf(v3*alpha);
                cs[nf][0] += v0 + v2; cs[nf][1] += v1 + v3;
            }
            float2 s01; s01.x = v0; s01.y = v1;
            float2 s23; s23.x = v2; s23.y = v3;
            *reinterpret_cast<float2*>(pC + (size_t)rg*ldc + col) = s01;
            *reinterpret_cast<float2*>(pC + (size_t)(rg+8)*ldc + col) = s23;
        }
    }
    if (EPI == 1) {
        #pragma unroll
        for (int o = 4; o <= 16; o <<= 1)
            #pragma unroll
            for (int nf = 0; nf < NF; nf++) {
                cs[nf][0] += __shfl_xor_sync(0xffffffffu, cs[nf][0], o);
                cs[nf][1] += __shfl_xor_sync(0xffffffffu, cs[nf][1], o);
            }
        if (lane < 4) {
            #pragma unroll
            for (int nf = 0; nf < NF; nf++) {
                int lc = wc*WN + nf*8 + lane*2;
                sZ[wr*BN + lc]     = cs[nf][0];
                sZ[wr*BN + lc + 1] = cs[nf][1];
            }
        }
        __syncthreads();
        for (int c = tid; c < BN; c += 256) {
            float s = sZ[c] + sZ[BN + c] + sZ[2*BN + c] + sZ[3*BN + c];
            Zpart[((size_t)z*gridDim.y + blockIdx.y)*TS + col0 + c] = s;
        }
    }
}

// ---------------- small fp32 kernels ----------------
__global__ void pack_wqkvT(const float* __restrict__ Wq, const float* __restrict__ Wk,
                           const float* __restrict__ Wv, float* __restrict__ o) {
    size_t idx = (size_t)blockIdx.x*256 + threadIdx.x;  // 3072*1024
    int n = (int)(idx >> 10), d = (int)(idx & 1023);
    const float* W = (n < DM) ? Wq : ((n < 2*DM) ? Wk : Wv);
    int nn = n & (DM-1), h = nn >> 6, kk = nn & 63;
    o[idx] = __ldg(&W[((size_t)h*DM + d)*HD + kk]);
}

__global__ void transpose_f32(const float* __restrict__ in, float* __restrict__ o,
                              int R, int C) {
    __shared__ float t[32][33];
    int r0 = blockIdx.y*32, c0 = blockIdx.x*32;
    int tx = threadIdx.x, ty = threadIdx.y;
    #pragma unroll
    for (int i = 0; i < 32; i += 8)
        t[ty+i][tx] = in[(size_t)(r0+ty+i)*C + c0 + tx];
    __syncthreads();
    #pragma unroll
    for (int i = 0; i < 32; i += 8)
        o[(size_t)(c0+ty+i)*R + r0 + tx] = t[tx][ty+i];
}

__global__ void zreduce(const float* __restrict__ Zpart, float* __restrict__ Zr) {
    int i = blockIdx.x*256 + threadIdx.x;
    int bh = i / TS, s = i % TS;
    float zv = 0.f;
    #pragma unroll
    for (int y = 0; y < 16; y++) zv += Zpart[((size_t)bh*16 + y)*TS + s];
    Zr[i] = 1.f / zv;
}

__global__ void vscale(const float* __restrict__ qkv, const float* __restrict__ Zr,
                       float* __restrict__ vt) {
    __shared__ float t[32][33];
    int bh = blockIdx.z, b = bh >> 4, h = bh & 15;
    int s0 = blockIdx.x*32, v0 = blockIdx.y*32;
    int tx = threadIdx.x, ty = threadIdx.y;
    #pragma unroll
    for (int i = 0; i < 32; i += 8) {
        int s = s0 + ty + i, v = v0 + tx;
        t[ty+i][tx] = qkv[(size_t)(b*TS + s)*(3*DM) + 2*DM + h*HD + v]
                      * Zr[(size_t)bh*TS + s];
    }
    __syncthreads();
    #pragma unroll
    for (int i = 0; i < 32; i += 8) {
        int v = v0 + ty + i, s = s0 + tx;
        vt[((size_t)bh*HD + v)*TS + s] = t[tx][ty+i];
    }
}

__device__ __forceinline__ float blk_sum(float v, float* sh) {
    int lane = threadIdx.x & 31, warp = threadIdx.x >> 5;
    #pragma unroll
    for (int o = 16; o; o >>= 1) v += __shfl_xor_sync(0xffffffffu, v, o);
    if (lane == 0) sh[warp] = v;
    __syncthreads();
    if (warp == 0) {
        v = (lane < 8) ? sh[lane] : 0.f;
        #pragma unroll
        for (int o = 16; o; o >>= 1) v += __shfl_xor_sync(0xffffffffu, v, o);
        if (lane == 0) sh[0] = v;
    }
    __syncthreads();
    float r = sh[0];
    __syncthreads();
    return r;
}

__global__ void add_norm(const float* __restrict__ A, const float* __restrict__ B,
                         float* __restrict__ out) {
    __shared__ float sh[32];
    size_t row = blockIdx.x;
    const float* pa = A + row*DM;
    const float* pb = B + row*DM;
    float v[4], s = 0.f;
    #pragma unroll
    for (int i = 0; i < 4; i++) {
        int c = threadIdx.x + i*256;
        v[i] = pa[c] + pb[c];
        s += v[i];
    }
    float mean = blk_sum(s, sh) * (1.f/(float)DM);
    float ss = 0.f;
    #pragma unroll
    for (int i = 0; i < 4; i++) { float d = v[i]-mean; ss += d*d; }
    float rstd = rsqrtf(blk_sum(ss, sh) * (1.f/(float)(DM-1)));
    #pragma unroll
    for (int i = 0; i < 4; i++) {
        int c = threadIdx.x + i*256;
        out[row*DM + c] = (v[i]-mean)*rstd;
    }
}

// ---------------- launch ----------------
extern "C" void kernel_launch(void* const* d_in, const int* in_sizes, int n_in,
                              void* d_out, int out_size) {
    const float* x  = (const float*)d_in[0];
    const float* Wq = (const float*)d_in[1];
    const float* Wk = (const float*)d_in[2];
    const float* Wv = (const float*)d_in[3];
    const float* Wo = (const float*)d_in[4];
    const float* W1 = (const float*)d_in[5];
    const float* b1 = (const float*)d_in[6];
    const float* W2 = (const float*)d_in[7];
    const float* b2 = (const float*)d_in[8];
    float* out = (float*)d_out;

    float *WqkvT,*WoT,*W1T,*W2T,*qkv,*scores,*Zp,*Zr,*vt,*obuf,*proj,*out1,*h1,*ff;
    cudaGetSymbolAddress((void**)&WqkvT, g_WqkvT);
    cudaGetSymbolAddress((void**)&WoT, g_WoT);
    cudaGetSymbolAddress((void**)&W1T, g_W1T);
    cudaGetSymbolAddress((void**)&W2T, g_W2T);
    cudaGetSymbolAddress((void**)&qkv, g_qkv);
    cudaGetSymbolAddress((void**)&scores, g_scores);
    cudaGetSymbolAddress((void**)&Zp, g_Zpart);
    cudaGetSymbolAddress((void**)&Zr, g_Zr);
    cudaGetSymbolAddress((void**)&vt, g_vt);
    cudaGetSymbolAddress((void**)&obuf, g_obuf);
    cudaGetSymbolAddress((void**)&proj, g_proj);
    cudaGetSymbolAddress((void**)&out1, g_out1);
    cudaGetSymbolAddress((void**)&h1, g_h1);
    cudaGetSymbolAddress((void**)&ff, g_ff);

    const int SM128 = 2*(2*128*40 + 2*128*40)*2 + 4*128*4;  // 83968
    const int SM64  = 2*(2*128*40 + 2*64*40)*2  + 4*64*4;   // 62464
    cudaFuncSetAttribute(mma_gemm<128,0>, cudaFuncAttributeMaxDynamicSharedMemorySize, SM128);
    cudaFuncSetAttribute(mma_gemm<128,1>, cudaFuncAttributeMaxDynamicSharedMemorySize, SM128);
    cudaFuncSetAttribute(mma_gemm<128,2>, cudaFuncAttributeMaxDynamicSharedMemorySize, SM128);
    cudaFuncSetAttribute(mma_gemm<128,3>, cudaFuncAttributeMaxDynamicSharedMemorySize, SM128);
    cudaFuncSetAttribute(mma_gemm<64,0>,  cudaFuncAttributeMaxDynamicSharedMemorySize, SM64);

    const long long TT = (long long)TS*TS;

    // weight prep (fp32, [N][K] layouts)
    pack_wqkvT<<<(3*DM*DM)/256, 256>>>(Wq, Wk, Wv, WqkvT);
    transpose_f32<<<dim3(DM/32, DM/32), dim3(32,8)>>>(Wo, WoT, DM, DM);
    transpose_f32<<<dim3(FFD/32, DM/32), dim3(32,8)>>>(W1, W1T, DM, FFD);
    transpose_f32<<<dim3(DM/32, FFD/32), dim3(32,8)>>>(W2, W2T, FFD, DM);

    // QKV = X @ WqkvT^T   (4096x3072, K=1024)
    mma_gemm<128,0><<<dim3(3*DM/128, BT/128, 1), 256, SM128>>>(
        x, WqkvT, qkv, nullptr, nullptr,
        DM, DM, DM, 3*DM, 0,0, 0,0, 0,0, 1, 1.0f);

    // scores = exp(Q @ K^T / 8) + column partial sums; batched over (b,h)
    mma_gemm<128,1><<<dim3(TS/128, TS/128, NBH), 256, SM128>>>(
        qkv, qkv + DM, scores, nullptr, Zp,
        HD, 3*DM, 3*DM, TS,
        (long long)TS*3*DM, HD, (long long)TS*3*DM, HD,
        (long long)NH*TT, TT, NH, 0.125f);

    zreduce<<<(NBH*TS)/256, 256>>>(Zp, Zr);
    vscale<<<dim3(TS/32, HD/32, NBH), dim3(32,8)>>>(qkv, Zr, vt);

    // O = exp_scores @ (V/Z)^T   (per bh: 2048x64, K=2048)
    mma_gemm<64,0><<<dim3(1, TS/128, NBH), 256, SM64>>>(
        scores, vt, obuf, nullptr, nullptr,
        TS, TS, TS, DM,
        (long long)NH*TT, TT, (long long)NH*HD*TS, (long long)HD*TS,
        (long long)TS*DM, HD, NH, 1.0f);

    // proj = O @ WoT^T
    mma_gemm<128,0><<<dim3(DM/128, BT/128, 1), 256, SM128>>>(
        obuf, WoT, proj, nullptr, nullptr,
        DM, DM, DM, DM, 0,0, 0,0, 0,0, 1, 1.0f);

    add_norm<<<BT, 256>>>(proj, x, out1);

    // h1 = relu(out1 @ W1T^T + b1)
    mma_gemm<128,3><<<dim3(FFD/128, BT/128, 1), 256, SM128>>>(
        out1, W1T, h1, b1, nullptr,
        DM, DM, DM, FFD, 0,0, 0,0, 0,0, 1, 1.0f);

    // ff = h1 @ W2T^T + b2
    mma_gemm<128,2><<<dim3(DM/128, BT/128, 1), 256, SM128>>>(
        h1, W2T, ff, b2, nullptr,
        FFD, FFD, FFD, DM, 0,0, 0,0, 0,0, 1, 1.0f);

    add_norm<<<BT, 256>>>(ff, out1, out);
}

// round 7
// speedup vs baseline: 2.3677x; 1.0550x over previous
#include <cuda_runtime.h>
#include <cuda_bf16.h>
#include <cstdint>
typedef __nv_bfloat16 bf16;

#define BATCH 2
#define TS 2048
#define DM 1024
#define NH 16
#define HD 64
#define FFD 4096
#define BT (BATCH*TS)
#define NBH (BATCH*NH)

// ---------------- scratch planes (no allocation) ----------------
__device__ __align__(16) bf16 g_WqkvT_h[(size_t)3*DM*DM];
__device__ __align__(16) bf16 g_WqkvT_l[(size_t)3*DM*DM];
__device__ __align__(16) bf16 g_WoT_h[(size_t)DM*DM];
__device__ __align__(16) bf16 g_WoT_l[(size_t)DM*DM];
__device__ __align__(16) bf16 g_W1T_h[(size_t)FFD*DM];
__device__ __align__(16) bf16 g_W1T_l[(size_t)FFD*DM];
__device__ __align__(16) bf16 g_W2T_h[(size_t)DM*FFD];
__device__ __align__(16) bf16 g_W2T_l[(size_t)DM*FFD];
__device__ __align__(16) bf16 g_xp_h[(size_t)BT*DM];
__device__ __align__(16) bf16 g_xp_l[(size_t)BT*DM];
__device__ __align__(16) bf16 g_qkv_h[(size_t)BT*3*DM];
__device__ __align__(16) bf16 g_qkv_l[(size_t)BT*3*DM];
__device__ __align__(16) bf16 g_sc_h[(size_t)NBH*TS*TS];      // exp(QK/8), hi only
__device__ __align__(16) float g_Zpart[(size_t)NBH*16*TS];
__device__ __align__(16) float g_Zr[(size_t)NBH*TS];
__device__ __align__(16) bf16 g_vt_h[(size_t)NBH*HD*TS];
__device__ __align__(16) bf16 g_vt_l[(size_t)NBH*HD*TS];
__device__ __align__(16) bf16 g_ob_h[(size_t)BT*DM];
__device__ __align__(16) bf16 g_ob_l[(size_t)BT*DM];
__device__ __align__(16) float g_proj[(size_t)BT*DM];
__device__ __align__(16) float g_out1[(size_t)BT*DM];
__device__ __align__(16) bf16 g_o1_h[(size_t)BT*DM];
__device__ __align__(16) bf16 g_o1_l[(size_t)BT*DM];
__device__ __align__(16) bf16 g_h1_h[(size_t)BT*FFD];
__device__ __align__(16) bf16 g_h1_l[(size_t)BT*FFD];
__device__ __align__(16) float g_ff[(size_t)BT*DM];

// ---------------- helpers ----------------
__device__ __forceinline__ uint32_t smem_u32(const void* p) {
    uint32_t a;
    asm("{ .reg .u64 t; cvta.to.shared.u64 t, %1; cvt.u32.u64 %0, t; }" : "=r"(a) : "l"(p));
    return a;
}
__device__ __forceinline__ void ldsm4(uint32_t (&r)[4], uint32_t addr) {
    asm volatile("ldmatrix.sync.aligned.m8n8.x4.shared.b16 {%0,%1,%2,%3}, [%4];"
        : "=r"(r[0]), "=r"(r[1]), "=r"(r[2]), "=r"(r[3]) : "r"(addr));
}
__device__ __forceinline__ void mma16816(float (&d)[4], const uint32_t (&a)[4],
                                         const uint32_t* b) {
    asm volatile("mma.sync.aligned.m16n8k16.row.col.f32.bf16.bf16.f32 "
        "{%0,%1,%2,%3}, {%4,%5,%6,%7}, {%8,%9}, {%0,%1,%2,%3};"
        : "+f"(d[0]), "+f"(d[1]), "+f"(d[2]), "+f"(d[3])
        : "r"(a[0]), "r"(a[1]), "r"(a[2]), "r"(a[3]), "r"(b[0]), "r"(b[1]));
}
#define CP16(dst, src) asm volatile("cp.async.cg.shared.global [%0], [%1], 16;" :: "r"(dst), "l"(src) : "memory")
#define CPC()  asm volatile("cp.async.commit_group;" ::: "memory")
#define CPW1() asm volatile("cp.async.wait_group 1;" ::: "memory")
#define CPW0() asm volatile("cp.async.wait_group 0;" ::: "memory")

__device__ __forceinline__ uint32_t pack2(bf16 a, bf16 b) {
    __nv_bfloat162 t; t.x = a; t.y = b;
    return *reinterpret_cast<uint32_t*>(&t);
}
__device__ __forceinline__ void cvt2(float a, float b, uint32_t& hi, uint32_t& lo) {
    bf16 h0 = __float2bfloat16(a), h1 = __float2bfloat16(b);
    hi = pack2(h0, h1);
    lo = pack2(__float2bfloat16(a - __bfloat162float(h0)),
               __float2bfloat16(b - __bfloat162float(h1)));
}
__device__ __forceinline__ void splitw(float x, bf16* oh, bf16* ol, size_t i) {
    bf16 h = __float2bfloat16(x);
    oh[i] = h; ol[i] = __float2bfloat16(x - __bfloat162float(h));
}

// ---------------- plane GEMM: C = f(alpha * A @ B^T) ----------------
// A planes [M][K] (lda), B planes [N][K] (ldb), all bf16.
// MODE bits: 1=fp32 out, 2=hi/lo plane out, 4=exp->hi-only plane + Zpart, 8=bias, 16=relu
template<int BN, int MODE, bool A2>
__global__ void __launch_bounds__(256, 1)
mma_gemm(const bf16* __restrict__ Ah, const bf16* __restrict__ Al,
         const bf16* __restrict__ Bh, const bf16* __restrict__ Bl,
         float* __restrict__ Cf, bf16* __restrict__ Ch, bf16* __restrict__ Cl,
         const float* __restrict__ bias, float* __restrict__ Zpart,
         int K, int lda, int ldb, int ldc,
         long long sA1, long long sA2, long long sB1, long long sB2,
         long long sC1, long long sC2, int zInner, float alpha)
{
    constexpr int BM = 128, WC = 2, WN = BN/WC, NF = WN/8;
    constexpr int LDT = 40;                         // 80B rows: ldmatrix conflict-free
    constexpr int NPA = A2 ? 2 : 1;
    constexpr int APL = BM*LDT, BPL = BN*LDT;       // elems per plane
    constexpr int SSZ = NPA*APL + 2*BPL;            // elems per stage
    constexpr int NGA = NPA*BM*4/256, NGB = 2*BN*4/256;

    extern __shared__ char dsm[];
    float* sZ = (float*)(dsm + (size_t)2*SSZ*2);
    const uint32_t sbase = smem_u32(dsm);

    const int tid = threadIdx.x, wid = tid >> 5, lane = tid & 31;
    const int wr = wid & 3, wc = wid >> 2, g = lane >> 2, tig = lane & 3;
    const int z = blockIdx.z, z1 = z / zInner, z2 = z % zInner;
    const int row0 = blockIdx.y * BM, col0 = blockIdx.x * BN;
    const bf16* pAh = Ah + z1*sA1 + z2*sA2 + (size_t)row0*lda;
    const bf16* pAl = A2 ? (Al + z1*sA1 + z2*sA2 + (size_t)row0*lda) : nullptr;
    const bf16* pBh = Bh + z1*sB1 + z2*sB2 + (size_t)col0*ldb;
    const bf16* pBl = Bl + z1*sB1 + z2*sB2 + (size_t)col0*ldb;

    float acc[2][NF][4];
    #pragma unroll
    for (int mf = 0; mf < 2; mf++)
        #pragma unroll
        for (int nf = 0; nf < NF; nf++)
            #pragma unroll
            for (int q = 0; q < 4; q++) acc[mf][nf][q] = 0.f;

    const int NC = K >> 5;

    auto loadS = [&](int c, int buf) {
        const uint32_t sb = sbase + (uint32_t)buf*SSZ*2;
        const int k0 = c << 5;
        #pragma unroll
        for (int i = 0; i < NGA; i++) {
            int gi = tid + i*256;
            int p = gi >> 9, rem = gi & 511, r = rem >> 2, q = rem & 3;
            const bf16* src = (p ? pAl : pAh) + (size_t)r*lda + k0 + q*8;
            CP16(sb + (uint32_t)(p*APL + r*LDT + q*8)*2, src);
        }
        #pragma unroll
        for (int i = 0; i < NGB; i++) {
            int gi = tid + i*256;
            int p = gi / (BN*4), rem = gi % (BN*4), r = rem >> 2, q = rem & 3;
            const bf16* src = (p ? pBl : pBh) + (size_t)r*ldb + k0 + q*8;
            CP16(sb + (uint32_t)(NPA*APL + p*BPL + r*LDT + q*8)*2, src);
        }
        CPC();
    };

    auto comp = [&](int buf) {
        const uint32_t aB = sbase + (uint32_t)buf*SSZ*2;
        const uint32_t alB = aB + APL*2;
        const uint32_t bB = aB + NPA*APL*2, blB = bB + BPL*2;
        #pragma unroll
        for (int ks = 0; ks < 2; ks++) {
            uint32_t ah[2][4], al[2][4], bh[NF][2], bl[NF][2];
            #pragma unroll
            for (int mf = 0; mf < 2; mf++) {
                int row = wr*32 + mf*16 + (lane & 15);
                int kc  = ks*16 + ((lane >> 4) << 3);
                uint32_t off = (uint32_t)(row*LDT + kc)*2;
                ldsm4(ah[mf], aB + off);
                if (A2) ldsm4(al[mf], alB + off);
            }
            #pragma unroll
            for (int nq = 0; nq < NF/2; nq++) {
                int n  = wc*WN + nq*16 + (lane & 7) + ((lane >> 4) << 3);
                int kc = ks*16 + (((lane >> 3) & 1) << 3);
                uint32_t off = (uint32_t)(n*LDT + kc)*2, t[4];
                ldsm4(t, bB + off);
                bh[2*nq][0]=t[0]; bh[2*nq][1]=t[1]; bh[2*nq+1][0]=t[2]; bh[2*nq+1][1]=t[3];
                ldsm4(t, blB + off);
                bl[2*nq][0]=t[0]; bl[2*nq][1]=t[1]; bl[2*nq+1][0]=t[2]; bl[2*nq+1][1]=t[3];
            }
            #pragma unroll
            for (int mf = 0; mf < 2; mf++)
                #pragma unroll
                for (int nf = 0; nf < NF; nf++) {
                    mma16816(acc[mf][nf], ah[mf], bh[nf]);
                    mma16816(acc[mf][nf], ah[mf], bl[nf]);
                    if (A2) mma16816(acc[mf][nf], al[mf], bh[nf]);
                }
        }
    };

    loadS(0, 0);
    if (NC > 1) loadS(1, 1);
    for (int c = 0; c < NC; c++) {
        if (c + 1 < NC) { CPW1(); } else { CPW0(); }
        __syncthreads();
        comp(c & 1);
        __syncthreads();
        if (c + 2 < NC) loadS(c + 2, c & 1);
    }

    // ---- epilogue ----
    float* pCf = (MODE & 1) ? (Cf + z1*sC1 + z2*sC2) : nullptr;
    bf16* pCh = (MODE & 6) ? (Ch + z1*sC1 + z2*sC2) : nullptr;
    bf16* pCl = (MODE & 2) ? (Cl + z1*sC1 + z2*sC2) : nullptr;
    float cs[NF][2];
    if (MODE & 4)
        #pragma unroll
        for (int nf = 0; nf < NF; nf++) { cs[nf][0] = 0.f; cs[nf][1] = 0.f; }

    #pragma unroll
    for (int mf = 0; mf < 2; mf++) {
        int rg = row0 + wr*32 + mf*16 + g;
        #pragma unroll
        for (int nf = 0; nf < NF; nf++) {
            int col = col0 + wc*WN + nf*8 + tig*2;
            float v0 = acc[mf][nf][0], v1 = acc[mf][nf][1];
            float v2 = acc[mf][nf][2], v3 = acc[mf][nf][3];
            if (MODE & 8) {
                float b0 = __ldg(bias + col), b1 = __ldg(bias + col + 1);
                v0 += b0; v1 += b1; v2 += b0; v3 += b1;
            }
            if (MODE & 16) {
                v0 = fmaxf(v0, 0.f); v1 = fmaxf(v1, 0.f);
                v2 = fmaxf(v2, 0.f); v3 = fmaxf(v3, 0.f);
            }
            if (MODE & 4) {
                bf16 e0 = __float2bfloat16(__expf(v0*alpha));
                bf16 e1 = __float2bfloat16(__expf(v1*alpha));
                bf16 e2 = __float2bfloat16(__expf(v2*alpha));
                bf16 e3 = __float2bfloat16(__expf(v3*alpha));
                cs[nf][0] += __bfloat162float(e0) + __bfloat162float(e2);
                cs[nf][1] += __bfloat162float(e1) + __bfloat162float(e3);
                *reinterpret_cast<uint32_t*>(pCh + (size_t)rg*ldc + col)     = pack2(e0, e1);
                *reinterpret_cast<uint32_t*>(pCh + (size_t)(rg+8)*ldc + col) = pack2(e2, e3);
            } else if (MODE & 2) {
                uint32_t h, l;
                cvt2(v0, v1, h, l);
                *reinterpret_cast<uint32_t*>(pCh + (size_t)rg*ldc + col) = h;
                *reinterpret_cast<uint32_t*>(pCl + (size_t)rg*ldc + col) = l;
                cvt2(v2, v3, h, l);
                *reinterpret_cast<uint32_t*>(pCh + (size_t)(rg+8)*ldc + col) = h;
                *reinterpret_cast<uint32_t*>(pCl + (size_t)(rg+8)*ldc + col) = l;
            }
            if (MODE & 1) {
                float2 s01; s01.x = v0; s01.y = v1;
                float2 s23; s23.x = v2; s23.y = v3;
                *reinterpret_cast<float2*>(pCf + (size_t)rg*ldc + col) = s01;
                *reinterpret_cast<float2*>(pCf + (size_t)(rg+8)*ldc + col) = s23;
            }
        }
    }
    if (MODE & 4) {
        #pragma unroll
        for (int o = 4; o <= 16; o <<= 1)
            #pragma unroll
            for (int nf = 0; nf < NF; nf++) {
                cs[nf][0] += __shfl_xor_sync(0xffffffffu, cs[nf][0], o);
                cs[nf][1] += __shfl_xor_sync(0xffffffffu, cs[nf][1], o);
            }
        if (lane < 4) {
            #pragma unroll
            for (int nf = 0; nf < NF; nf++) {
                int lc = wc*WN + nf*8 + lane*2;
                sZ[wr*BN + lc]     = cs[nf][0];
                sZ[wr*BN + lc + 1] = cs[nf][1];
            }
        }
        __syncthreads();
        for (int c = tid; c < BN; c += 256) {
            float s = sZ[c] + sZ[BN + c] + sZ[2*BN + c] + sZ[3*BN + c];
            Zpart[((size_t)z*gridDim.y + blockIdx.y)*TS + col0 + c] = s;
        }
    }
}

// ---------------- prep / elementwise kernels ----------------
__global__ void split_x(const float* __restrict__ in, bf16* __restrict__ oh,
                        bf16* __restrict__ ol) {
    size_t i = (size_t)blockIdx.x*256 + threadIdx.x;
    splitw(in[i], oh, ol, i);
}
__global__ void pack_wqkvT(const float* __restrict__ Wq, const float* __restrict__ Wk,
                           const float* __restrict__ Wv, bf16* __restrict__ oh,
                           bf16* __restrict__ ol) {
    size_t idx = (size_t)blockIdx.x*256 + threadIdx.x;  // 3072*1024
    int n = (int)(idx >> 10), d = (int)(idx & 1023);
    const float* W = (n < DM) ? Wq : ((n < 2*DM) ? Wk : Wv);
    int nn = n & (DM-1), h = nn >> 6, kk = nn & 63;
    splitw(__ldg(&W[((size_t)h*DM + d)*HD + kk]), oh, ol, idx);
}
__global__ void transpose_split(const float* __restrict__ in, bf16* __restrict__ oh,
                                bf16* __restrict__ ol, int R, int C) {
    __shared__ float t[32][33];
    int r0 = blockIdx.y*32, c0 = blockIdx.x*32;
    int tx = threadIdx.x, ty = threadIdx.y;
    #pragma unroll
    for (int i = 0; i < 32; i += 8)
        t[ty+i][tx] = in[(size_t)(r0+ty+i)*C + c0 + tx];
    __syncthreads();
    #pragma unroll
    for (int i = 0; i < 32; i += 8)
        splitw(t[tx][ty+i], oh, ol, (size_t)(c0+ty+i)*R + r0 + tx);
}
__global__ void zreduce(const float* __restrict__ Zpart, float* __restrict__ Zr) {
    int i = blockIdx.x*256 + threadIdx.x;
    int bh = i / TS, s = i % TS;
    float zv = 0.f;
    #pragma unroll
    for (int y = 0; y < 16; y++) zv += Zpart[((size_t)bh*16 + y)*TS + s];
    Zr[i] = 1.f / zv;
}
__global__ void vscale(const bf16* __restrict__ qh, const bf16* __restrict__ ql,
                       const float* __restrict__ Zr, bf16* __restrict__ oh,
                       bf16* __restrict__ ol) {
    __shared__ float t[32][33];
    int bh = blockIdx.z, b = bh >> 4, h = bh & 15;
    int s0 = blockIdx.x*32, v0 = blockIdx.y*32;
    int tx = threadIdx.x, ty = threadIdx.y;
    #pragma unroll
    for (int i = 0; i < 32; i += 8) {
        int s = s0 + ty + i, v = v0 + tx;
        size_t o = (size_t)(b*TS + s)*(3*DM) + 2*DM + h*HD + v;
        t[ty+i][tx] = (__bfloat162float(qh[o]) + __bfloat162float(ql[o]))
                      * Zr[(size_t)bh*TS + s];
    }
    __syncthreads();
    #pragma unroll
    for (int i = 0; i < 32; i += 8) {
        int v = v0 + ty + i, s = s0 + tx;
        splitw(t[tx][ty+i], oh, ol, ((size_t)bh*HD + v)*TS + s);
    }
}
__device__ __forceinline__ float blk_sum(float v, float* sh) {
    int lane = threadIdx.x & 31, warp = threadIdx.x >> 5;
    #pragma unroll
    for (int o = 16; o; o >>= 1) v += __shfl_xor_sync(0xffffffffu, v, o);
    if (lane == 0) sh[warp] = v;
    __syncthreads();
    if (warp == 0) {
        v = (lane < 8) ? sh[lane] : 0.f;
        #pragma unroll
        for (int o = 16; o; o >>= 1) v += __shfl_xor_sync(0xffffffffu, v, o);
        if (lane == 0) sh[0] = v;
    }
    __syncthreads();
    float r = sh[0];
    __syncthreads();
    return r;
}
template<bool PL>
__global__ void add_norm(const float* __restrict__ A, const float* __restrict__ B,
                         float* __restrict__ out, bf16* __restrict__ oh,
                         bf16* __restrict__ ol) {
    __shared__ float sh[32];
    size_t row = blockIdx.x;
    const float* pa = A + row*DM;
    const float* pb = B + row*DM;
    float v[4], s = 0.f;
    #pragma unroll
    for (int i = 0; i < 4; i++) {
        int c = threadIdx.x + i*256;
        v[i] = pa[c] + pb[c];
        s += v[i];
    }
    float mean = blk_sum(s, sh) * (1.f/(float)DM);
    float ss = 0.f;
    #pragma unroll
    for (int i = 0; i < 4; i++) { float d = v[i]-mean; ss += d*d; }
    float rstd = rsqrtf(blk_sum(ss, sh) * (1.f/(float)(DM-1)));
    #pragma unroll
    for (int i = 0; i < 4; i++) {
        int c = threadIdx.x + i*256;
        float y = (v[i]-mean)*rstd;
        out[row*DM + c] = y;
        if (PL) splitw(y, oh, ol, row*DM + c);
    }
}

// ---------------- launch ----------------
extern "C" void kernel_launch(void* const* d_in, const int* in_sizes, int n_in,
                              void* d_out, int out_size) {
    const float* x  = (const float*)d_in[0];
    const float* Wq = (const float*)d_in[1];
    const float* Wk = (const float*)d_in[2];
    const float* Wv = (const float*)d_in[3];
    const float* Wo = (const float*)d_in[4];
    const float* W1 = (const float*)d_in[5];
    const float* b1 = (const float*)d_in[6];
    const float* W2 = (const float*)d_in[7];
    const float* b2 = (const float*)d_in[8];
    float* out = (float*)d_out;

    bf16 *WqkvTh,*WqkvTl,*WoTh,*WoTl,*W1Th,*W1Tl,*W2Th,*W2Tl,*xph,*xpl;
    bf16 *qh,*ql,*sch,*vth,*vtl,*obh,*obl,*o1h,*o1l,*h1h,*h1l;
    float *Zp,*Zr,*proj,*out1,*ff;
    cudaGetSymbolAddress((void**)&WqkvTh, g_WqkvT_h); cudaGetSymbolAddress((void**)&WqkvTl, g_WqkvT_l);
    cudaGetSymbolAddress((void**)&WoTh, g_WoT_h);     cudaGetSymbolAddress((void**)&WoTl, g_WoT_l);
    cudaGetSymbolAddress((void**)&W1Th, g_W1T_h);     cudaGetSymbolAddress((void**)&W1Tl, g_W1T_l);
    cudaGetSymbolAddress((void**)&W2Th, g_W2T_h);     cudaGetSymbolAddress((void**)&W2Tl, g_W2T_l);
    cudaGetSymbolAddress((void**)&xph, g_xp_h);       cudaGetSymbolAddress((void**)&xpl, g_xp_l);
    cudaGetSymbolAddress((void**)&qh, g_qkv_h);       cudaGetSymbolAddress((void**)&ql, g_qkv_l);
    cudaGetSymbolAddress((void**)&sch, g_sc_h);
    cudaGetSymbolAddress((void**)&vth, g_vt_h);       cudaGetSymbolAddress((void**)&vtl, g_vt_l);
    cudaGetSymbolAddress((void**)&obh, g_ob_h);       cudaGetSymbolAddress((void**)&obl, g_ob_l);
    cudaGetSymbolAddress((void**)&o1h, g_o1_h);       cudaGetSymbolAddress((void**)&o1l, g_o1_l);
    cudaGetSymbolAddress((void**)&h1h, g_h1_h);       cudaGetSymbolAddress((void**)&h1l, g_h1_l);
    cudaGetSymbolAddress((void**)&Zp, g_Zpart);       cudaGetSymbolAddress((void**)&Zr, g_Zr);
    cudaGetSymbolAddress((void**)&proj, g_proj);      cudaGetSymbolAddress((void**)&out1, g_out1);
    cudaGetSymbolAddress((void**)&ff, g_ff);

    const int SMF = 2*(2*128*40 + 2*128*40)*2 + 2048;   // 83968 (A2, BN=128)
    const int SMA = 2*(1*128*40 + 2*64*40)*2 + 2048;    // 43008 (attn-V)
    cudaFuncSetAttribute(mma_gemm<128,2,true>,  cudaFuncAttributeMaxDynamicSharedMemorySize, SMF);
    cudaFuncSetAttribute(mma_gemm<128,4,true>,  cudaFuncAttributeMaxDynamicSharedMemorySize, SMF);
    cudaFuncSetAttribute(mma_gemm<64,2,false>,  cudaFuncAttributeMaxDynamicSharedMemorySize, SMA);
    cudaFuncSetAttribute(mma_gemm<128,1,true>,  cudaFuncAttributeMaxDynamicSharedMemorySize, SMF);
    cudaFuncSetAttribute(mma_gemm<128,26,true>, cudaFuncAttributeMaxDynamicSharedMemorySize, SMF);
    cudaFuncSetAttribute(mma_gemm<128,9,true>,  cudaFuncAttributeMaxDynamicSharedMemorySize, SMF);

    const long long TT = (long long)TS*TS;

    // prep: planes for x + all weights
    split_x<<<(BT*DM)/256, 256>>>(x, xph, xpl);
    pack_wqkvT<<<(3*DM*DM)/256, 256>>>(Wq, Wk, Wv, WqkvTh, WqkvTl);
    transpose_split<<<dim3(DM/32, DM/32), dim3(32,8)>>>(Wo, WoTh, WoTl, DM, DM);
    transpose_split<<<dim3(FFD/32, DM/32), dim3(32,8)>>>(W1, W1Th, W1Tl, DM, FFD);
    transpose_split<<<dim3(DM/32, FFD/32), dim3(32,8)>>>(W2, W2Th, W2Tl, FFD, DM);

    // QKV = X @ WqkvT^T -> planes (4096x3072, K=1024)
    mma_gemm<128,2,true><<<dim3(3*DM/128, BT/128, 1), 256, SMF>>>(
        xph, xpl, WqkvTh, WqkvTl, nullptr, qh, ql, nullptr, nullptr,
        DM, DM, DM, 3*DM, 0,0, 0,0, 0,0, 1, 1.0f);

    // scores = exp(Q @ K^T / 8) hi-only + column sums; batched over (b,h)
    mma_gemm<128,4,true><<<dim3(TS/128, TS/128, NBH), 256, SMF>>>(
        qh, ql, qh + DM, ql + DM, nullptr, sch, nullptr, nullptr, Zp,
        HD, 3*DM, 3*DM, TS,
        (long long)TS*3*DM, HD, (long long)TS*3*DM, HD,
        (long long)NH*TT, TT, NH, 0.125f);

    zreduce<<<(NBH*TS)/256, 256>>>(Zp, Zr);
    vscale<<<dim3(TS/32, HD/32, NBH), dim3(32,8)>>>(qh, ql, Zr, vth, vtl);

    // O = scores_hi @ (V/Z)^T -> planes (per bh: 2048x64, K=2048)
    mma_gemm<64,2,false><<<dim3(1, TS/128, NBH), 256, SMA>>>(
        sch, nullptr, vth, vtl, nullptr, obh, obl, nullptr, nullptr,
        TS, TS, TS, DM,
        (long long)NH*TT, TT, (long long)NH*HD*TS, (long long)HD*TS,
        (long long)TS*DM, HD, NH, 1.0f);

    // proj = O @ WoT^T (fp32)
    mma_gemm<128,1,true><<<dim3(DM/128, BT/128, 1), 256, SMF>>>(
        obh, obl, WoTh, WoTl, proj, nullptr, nullptr, nullptr, nullptr,
        DM, DM, DM, DM, 0,0, 0,0, 0,0, 1, 1.0f);

    add_norm<true><<<BT, 256>>>(proj, x, out1, o1h, o1l);

    // h1 = relu(out1 @ W1T^T + b1) -> planes
    mma_gemm<128,26,true><<<dim3(FFD/128, BT/128, 1), 256, SMF>>>(
        o1h, o1l, W1Th, W1Tl, nullptr, h1h, h1l, b1, nullptr,
        DM, DM, DM, FFD, 0,0, 0,0, 0,0, 1, 1.0f);

    // ff = h1 @ W2T^T + b2 (fp32)
    mma_gemm<128,9,true><<<dim3(DM/128, BT/128, 1), 256, SMF>>>(
        h1h, h1l, W2Th, W2Tl, ff, nullptr, nullptr, b2, nullptr,
        FFD, FFD, FFD, DM, 0,0, 0,0, 0,0, 1, 1.0f);

    add_norm<false><<<BT, 256>>>(ff, out1, out, nullptr, nullptr);
}

// round 8
// speedup vs baseline: 2.4387x; 1.0300x over previous
#include <cuda_runtime.h>
#include <cuda_bf16.h>
#include <cstdint>
typedef __nv_bfloat16 bf16;

#define BATCH 2
#define TS 2048
#define DM 1024
#define NH 16
#define HD 64
#define FFD 4096
#define BT (BATCH*TS)
#define NBH (BATCH*NH)

// ---------------- scratch planes (no allocation) ----------------
__device__ __align__(16) bf16 g_WqkvT_h[(size_t)3*DM*DM];
__device__ __align__(16) bf16 g_WqkvT_l[(size_t)3*DM*DM];
__device__ __align__(16) bf16 g_WoT_h[(size_t)DM*DM];
__device__ __align__(16) bf16 g_WoT_l[(size_t)DM*DM];
__device__ __align__(16) bf16 g_W1T_h[(size_t)FFD*DM];
__device__ __align__(16) bf16 g_W1T_l[(size_t)FFD*DM];
__device__ __align__(16) bf16 g_W2T_h[(size_t)DM*FFD];
__device__ __align__(16) bf16 g_W2T_l[(size_t)DM*FFD];
__device__ __align__(16) bf16 g_xp_h[(size_t)BT*DM];
__device__ __align__(16) bf16 g_xp_l[(size_t)BT*DM];
__device__ __align__(16) bf16 g_qkv_h[(size_t)BT*3*DM];
__device__ __align__(16) bf16 g_qkv_l[(size_t)BT*3*DM];
__device__ __align__(16) bf16 g_sc_h[(size_t)NBH*TS*TS];      // exp(QK/8), hi only
__device__ __align__(16) float g_Zpart[(size_t)NBH*16*TS];
__device__ __align__(16) float g_Zr[(size_t)NBH*TS];
__device__ __align__(16) bf16 g_vt_h[(size_t)NBH*HD*TS];
__device__ __align__(16) bf16 g_vt_l[(size_t)NBH*HD*TS];
__device__ __align__(16) bf16 g_ob_h[(size_t)BT*DM];
__device__ __align__(16) bf16 g_ob_l[(size_t)BT*DM];
__device__ __align__(16) float g_proj[(size_t)BT*DM];
__device__ __align__(16) float g_out1[(size_t)BT*DM];
__device__ __align__(16) bf16 g_o1_h[(size_t)BT*DM];
__device__ __align__(16) bf16 g_o1_l[(size_t)BT*DM];
__device__ __align__(16) bf16 g_h1_h[(size_t)BT*FFD];
__device__ __align__(16) bf16 g_h1_l[(size_t)BT*FFD];
__device__ __align__(16) float g_ff[(size_t)BT*DM];

// ---------------- helpers ----------------
__device__ __forceinline__ uint32_t smem_u32(const void* p) {
    uint32_t a;
    asm("{ .reg .u64 t; cvta.to.shared.u64 t, %1; cvt.u32.u64 %0, t; }" : "=r"(a) : "l"(p));
    return a;
}
__device__ __forceinline__ void ldsm4(uint32_t (&r)[4], uint32_t addr) {
    asm volatile("ldmatrix.sync.aligned.m8n8.x4.shared.b16 {%0,%1,%2,%3}, [%4];"
        : "=r"(r[0]), "=r"(r[1]), "=r"(r[2]), "=r"(r[3]) : "r"(addr));
}
__device__ __forceinline__ void mma16816(float (&d)[4], const uint32_t (&a)[4],
                                         const uint32_t* b) {
    asm volatile("mma.sync.aligned.m16n8k16.row.col.f32.bf16.bf16.f32 "
        "{%0,%1,%2,%3}, {%4,%5,%6,%7}, {%8,%9}, {%0,%1,%2,%3};"
        : "+f"(d[0]), "+f"(d[1]), "+f"(d[2]), "+f"(d[3])
        : "r"(a[0]), "r"(a[1]), "r"(a[2]), "r"(a[3]), "r"(b[0]), "r"(b[1]));
}
#define CP16(dst, src) asm volatile("cp.async.cg.shared.global [%0], [%1], 16;" :: "r"(dst), "l"(src) : "memory")
#define CPC()  asm volatile("cp.async.commit_group;" ::: "memory")
#define CPW1() asm volatile("cp.async.wait_group 1;" ::: "memory")
#define CPW0() asm volatile("cp.async.wait_group 0;" ::: "memory")

__device__ __forceinline__ uint32_t pack2(bf16 a, bf16 b) {
    __nv_bfloat162 t; t.x = a; t.y = b;
    return *reinterpret_cast<uint32_t*>(&t);
}
__device__ __forceinline__ void cvt2(float a, float b, uint32_t& hi, uint32_t& lo) {
    bf16 h0 = __float2bfloat16(a), h1 = __float2bfloat16(b);
    hi = pack2(h0, h1);
    lo = pack2(__float2bfloat16(a - __bfloat162float(h0)),
               __float2bfloat16(b - __bfloat162float(h1)));
}
__device__ __forceinline__ void splitw(float x, bf16* oh, bf16* ol, size_t i) {
    bf16 h = __float2bfloat16(x);
    oh[i] = h; ol[i] = __float2bfloat16(x - __bfloat162float(h));
}

// ---------------- plane GEMM: C = f(alpha * A @ B^T) ----------------
// A planes [M][K] (lda), B planes [N][K] (ldb), all bf16. 3-stage cp.async ring,
// ONE __syncthreads per K-chunk; prefetch issued before compute.
// MODE bits: 1=fp32 out, 2=hi/lo plane out, 4=exp->hi-only plane + Zpart, 8=bias, 16=relu
template<int BN, int MODE, bool A2>
__global__ void __launch_bounds__(256, 1)
mma_gemm(const bf16* __restrict__ Ah, const bf16* __restrict__ Al,
         const bf16* __restrict__ Bh, const bf16* __restrict__ Bl,
         float* __restrict__ Cf, bf16* __restrict__ Ch, bf16* __restrict__ Cl,
         const float* __restrict__ bias, float* __restrict__ Zpart,
         int K, int lda, int ldb, int ldc,
         long long sA1, long long sA2, long long sB1, long long sB2,
         long long sC1, long long sC2, int zInner, float alpha)
{
    constexpr int BM = 128, WC = 2, WN = BN/WC, NF = WN/8;
    constexpr int LDT = 40;                         // 80B rows: ldmatrix conflict-free
    constexpr int NPA = A2 ? 2 : 1;
    constexpr int APL = BM*LDT, BPL = BN*LDT;       // elems per plane
    constexpr int SSZ = NPA*APL + 2*BPL;            // elems per stage
    constexpr int NST = 3;                          // pipeline stages
    constexpr int NGA = NPA*BM*4/256, NGB = 2*BN*4/256;

    extern __shared__ char dsm[];
    float* sZ = (float*)(dsm + (size_t)NST*SSZ*2);
    const uint32_t sbase = smem_u32(dsm);

    const int tid = threadIdx.x, wid = tid >> 5, lane = tid & 31;
    const int wr = wid & 3, wc = wid >> 2, g = lane >> 2, tig = lane & 3;
    const int z = blockIdx.z, z1 = z / zInner, z2 = z % zInner;
    const int row0 = blockIdx.y * BM, col0 = blockIdx.x * BN;
    const bf16* pAh = Ah + z1*sA1 + z2*sA2 + (size_t)row0*lda;
    const bf16* pAl = A2 ? (Al + z1*sA1 + z2*sA2 + (size_t)row0*lda) : nullptr;
    const bf16* pBh = Bh + z1*sB1 + z2*sB2 + (size_t)col0*ldb;
    const bf16* pBl = Bl + z1*sB1 + z2*sB2 + (size_t)col0*ldb;

    float acc[2][NF][4];
    #pragma unroll
    for (int mf = 0; mf < 2; mf++)
        #pragma unroll
        for (int nf = 0; nf < NF; nf++)
            #pragma unroll
            for (int q = 0; q < 4; q++) acc[mf][nf][q] = 0.f;

    const int NC = K >> 5;

    auto loadS = [&](int c, int buf) {
        const uint32_t sb = sbase + (uint32_t)buf*SSZ*2;
        const int k0 = c << 5;
        #pragma unroll
        for (int i = 0; i < NGA; i++) {
            int gi = tid + i*256;
            int p = gi >> 9, rem = gi & 511, r = rem >> 2, q = rem & 3;
            const bf16* src = (p ? pAl : pAh) + (size_t)r*lda + k0 + q*8;
            CP16(sb + (uint32_t)(p*APL + r*LDT + q*8)*2, src);
        }
        #pragma unroll
        for (int i = 0; i < NGB; i++) {
            int gi = tid + i*256;
            int p = gi / (BN*4), rem = gi % (BN*4), r = rem >> 2, q = rem & 3;
            const bf16* src = (p ? pBl : pBh) + (size_t)r*ldb + k0 + q*8;
            CP16(sb + (uint32_t)(NPA*APL + p*BPL + r*LDT + q*8)*2, src);
        }
        CPC();
    };

    auto comp = [&](int buf) {
        const uint32_t aB = sbase + (uint32_t)buf*SSZ*2;
        const uint32_t alB = aB + APL*2;
        const uint32_t bB = aB + NPA*APL*2, blB = bB + BPL*2;
        #pragma unroll
        for (int ks = 0; ks < 2; ks++) {
            uint32_t ah[2][4], al[2][4], bh[NF][2], bl[NF][2];
            #pragma unroll
            for (int mf = 0; mf < 2; mf++) {
                int row = wr*32 + mf*16 + (lane & 15);
                int kc  = ks*16 + ((lane >> 4) << 3);
                uint32_t off = (uint32_t)(row*LDT + kc)*2;
                ldsm4(ah[mf], aB + off);
                if (A2) ldsm4(al[mf], alB + off);
            }
            #pragma unroll
            for (int nq = 0; nq < NF/2; nq++) {
                int n  = wc*WN + nq*16 + (lane & 7) + ((lane >> 4) << 3);
                int kc = ks*16 + (((lane >> 3) & 1) << 3);
                uint32_t off = (uint32_t)(n*LDT + kc)*2, t[4];
                ldsm4(t, bB + off);
                bh[2*nq][0]=t[0]; bh[2*nq][1]=t[1]; bh[2*nq+1][0]=t[2]; bh[2*nq+1][1]=t[3];
                ldsm4(t, blB + off);
                bl[2*nq][0]=t[0]; bl[2*nq][1]=t[1]; bl[2*nq+1][0]=t[2]; bl[2*nq+1][1]=t[3];
            }
            #pragma unroll
            for (int mf = 0; mf < 2; mf++)
                #pragma unroll
                for (int nf = 0; nf < NF; nf++) {
                    mma16816(acc[mf][nf], ah[mf], bh[nf]);
                    mma16816(acc[mf][nf], ah[mf], bl[nf]);
                    if (A2) mma16816(acc[mf][nf], al[mf], bh[nf]);
                }
        }
    };

    // 3-stage ring, one barrier per chunk:
    //  iter c: wait chunk c -> sync -> prefetch c+2 into (c+2)%3 -> compute c%3
    // (buffer (c+2)%3 was read by comp(c-1), fenced by this iter's sync)
    loadS(0, 0);
    if (NC > 1) loadS(1, 1);
    int bufc = 0, bufl = 2;                 // c%3 and (c+2)%3 trackers
    for (int c = 0; c < NC; c++) {
        if (c + 1 < NC) { CPW1(); } else { CPW0(); }
        __syncthreads();
        if (c + 2 < NC) loadS(c + 2, bufl);
        comp(bufc);
        bufc = (bufc == 2) ? 0 : bufc + 1;
        bufl = (bufl == 2) ? 0 : bufl + 1;
    }

    // ---- epilogue ----
    float* pCf = (MODE & 1) ? (Cf + z1*sC1 + z2*sC2) : nullptr;
    bf16* pCh = (MODE & 6) ? (Ch + z1*sC1 + z2*sC2) : nullptr;
    bf16* pCl = (MODE & 2) ? (Cl + z1*sC1 + z2*sC2) : nullptr;
    float cs[NF][2];
    if (MODE & 4)
        #pragma unroll
        for (int nf = 0; nf < NF; nf++) { cs[nf][0] = 0.f; cs[nf][1] = 0.f; }

    #pragma unroll
    for (int mf = 0; mf < 2; mf++) {
        int rg = row0 + wr*32 + mf*16 + g;
        #pragma unroll
        for (int nf = 0; nf < NF; nf++) {
            int col = col0 + wc*WN + nf*8 + tig*2;
            float v0 = acc[mf][nf][0], v1 = acc[mf][nf][1];
            float v2 = acc[mf][nf][2], v3 = acc[mf][nf][3];
            if (MODE & 8) {
                float b0 = __ldg(bias + col), b1 = __ldg(bias + col + 1);
                v0 += b0; v1 += b1; v2 += b0; v3 += b1;
            }
            if (MODE & 16) {
                v0 = fmaxf(v0, 0.f); v1 = fmaxf(v1, 0.f);
                v2 = fmaxf(v2, 0.f); v3 = fmaxf(v3, 0.f);
            }
            if (MODE & 4) {
                bf16 e0 = __float2bfloat16(__expf(v0*alpha));
                bf16 e1 = __float2bfloat16(__expf(v1*alpha));
                bf16 e2 = __float2bfloat16(__expf(v2*alpha));
                bf16 e3 = __float2bfloat16(__expf(v3*alpha));
                cs[nf][0] += __bfloat162float(e0) + __bfloat162float(e2);
                cs[nf][1] += __bfloat162float(e1) + __bfloat162float(e3);
                *reinterpret_cast<uint32_t*>(pCh + (size_t)rg*ldc + col)     = pack2(e0, e1);
                *reinterpret_cast<uint32_t*>(pCh + (size_t)(rg+8)*ldc + col) = pack2(e2, e3);
            } else if (MODE & 2) {
                uint32_t h, l;
                cvt2(v0, v1, h, l);
                *reinterpret_cast<uint32_t*>(pCh + (size_t)rg*ldc + col) = h;
                *reinterpret_cast<uint32_t*>(pCl + (size_t)rg*ldc + col) = l;
                cvt2(v2, v3, h, l);
                *reinterpret_cast<uint32_t*>(pCh + (size_t)(rg+8)*ldc + col) = h;
                *reinterpret_cast<uint32_t*>(pCl + (size_t)(rg+8)*ldc + col) = l;
            }
            if (MODE & 1) {
                float2 s01; s01.x = v0; s01.y = v1;
                float2 s23; s23.x = v2; s23.y = v3;
                *reinterpret_cast<float2*>(pCf + (size_t)rg*ldc + col) = s01;
                *reinterpret_cast<float2*>(pCf + (size_t)(rg+8)*ldc + col) = s23;
            }
        }
    }
    if (MODE & 4) {
        #pragma unroll
        for (int o = 4; o <= 16; o <<= 1)
            #pragma unroll
            for (int nf = 0; nf < NF; nf++) {
                cs[nf][0] += __shfl_xor_sync(0xffffffffu, cs[nf][0], o);
                cs[nf][1] += __shfl_xor_sync(0xffffffffu, cs[nf][1], o);
            }
        if (lane < 4) {
            #pragma unroll
            for (int nf = 0; nf < NF; nf++) {
                int lc = wc*WN + nf*8 + lane*2;
                sZ[wr*BN + lc]     = cs[nf][0];
                sZ[wr*BN + lc + 1] = cs[nf][1];
            }
        }
        __syncthreads();
        for (int c = tid; c < BN; c += 256) {
            float s = sZ[c] + sZ[BN + c] + sZ[2*BN + c] + sZ[3*BN + c];
            Zpart[((size_t)z*gridDim.y + blockIdx.y)*TS + col0 + c] = s;
        }
    }
}

// ---------------- prep / elementwise kernels ----------------
__global__ void split_x(const float* __restrict__ in, bf16* __restrict__ oh,
                        bf16* __restrict__ ol) {
    size_t i = (size_t)blockIdx.x*256 + threadIdx.x;
    splitw(in[i], oh, ol, i);
}
__global__ void pack_wqkvT(const float* __restrict__ Wq, const float* __restrict__ Wk,
                           const float* __restrict__ Wv, bf16* __restrict__ oh,
                           bf16* __restrict__ ol) {
    size_t idx = (size_t)blockIdx.x*256 + threadIdx.x;  // 3072*1024
    int n = (int)(idx >> 10), d = (int)(idx & 1023);
    const float* W = (n < DM) ? Wq : ((n < 2*DM) ? Wk : Wv);
    int nn = n & (DM-1), h = nn >> 6, kk = nn & 63;
    splitw(__ldg(&W[((size_t)h*DM + d)*HD + kk]), oh, ol, idx);
}
__global__ void transpose_split(const float* __restrict__ in, bf16* __restrict__ oh,
                                bf16* __restrict__ ol, int R, int C) {
    __shared__ float t[32][33];
    int r0 = blockIdx.y*32, c0 = blockIdx.x*32;
    int tx = threadIdx.x, ty = threadIdx.y;
    #pragma unroll
    for (int i = 0; i < 32; i += 8)
        t[ty+i][tx] = in[(size_t)(r0+ty+i)*C + c0 + tx];
    __syncthreads();
    #pragma unroll
    for (int i = 0; i < 32; i += 8)
        splitw(t[tx][ty+i], oh, ol, (size_t)(c0+ty+i)*R + r0 + tx);
}
__global__ void zreduce(const float* __restrict__ Zpart, float* __restrict__ Zr) {
    int i = blockIdx.x*256 + threadIdx.x;
    int bh = i / TS, s = i % TS;
    float zv = 0.f;
    #pragma unroll
    for (int y = 0; y < 16; y++) zv += Zpart[((size_t)bh*16 + y)*TS + s];
    Zr[i] = 1.f / zv;
}
__global__ void vscale(const bf16* __restrict__ qh, const bf16* __restrict__ ql,
                       const float* __restrict__ Zr, bf16* __restrict__ oh,
                       bf16* __restrict__ ol) {
    __shared__ float t[32][33];
    int bh = blockIdx.z, b = bh >> 4, h = bh & 15;
    int s0 = blockIdx.x*32, v0 = blockIdx.y*32;
    int tx = threadIdx.x, ty = threadIdx.y;
    #pragma unroll
    for (int i = 0; i < 32; i += 8) {
        int s = s0 + ty + i, v = v0 + tx;
        size_t o = (size_t)(b*TS + s)*(3*DM) + 2*DM + h*HD + v;
        t[ty+i][tx] = (__bfloat162float(qh[o]) + __bfloat162float(ql[o]))
                      * Zr[(size_t)bh*TS + s];
    }
    __syncthreads();
    #pragma unroll
    for (int i = 0; i < 32; i += 8) {
        int v = v0 + ty + i, s = s0 + tx;
        splitw(t[tx][ty+i], oh, ol, ((size_t)bh*HD + v)*TS + s);
    }
}
__device__ __forceinline__ float blk_sum(float v, float* sh) {
    int lane = threadIdx.x & 31, warp = threadIdx.x >> 5;
    #pragma unroll
    for (int o = 16; o; o >>= 1) v += __shfl_xor_sync(0xffffffffu, v, o);
    if (lane == 0) sh[warp] = v;
    __syncthreads();
    if (warp == 0) {
        v = (lane < 8) ? sh[lane] : 0.f;
        #pragma unroll
        for (int o = 16; o; o >>= 1) v += __shfl_xor_sync(0xffffffffu, v, o);
        if (lane == 0) sh[0] = v;
    }
    __syncthreads();
    float r = sh[0];
    __syncthreads();
    return r;
}
template<bool PL>
__global__ void add_norm(const float* __restrict__ A, const float* __restrict__ B,
                         float* __restrict__ out, bf16* __restrict__ oh,
                         bf16* __restrict__ ol) {
    __shared__ float sh[32];
    size_t row = blockIdx.x;
    const float* pa = A + row*DM;
    const float* pb = B + row*DM;
    float v[4], s = 0.f;
    #pragma unroll
    for (int i = 0; i < 4; i++) {
        int c = threadIdx.x + i*256;
        v[i] = pa[c] + pb[c];
        s += v[i];
    }
    float mean = blk_sum(s, sh) * (1.f/(float)DM);
    float ss = 0.f;
    #pragma unroll
    for (int i = 0; i < 4; i++) { float d = v[i]-mean; ss += d*d; }
    float rstd = rsqrtf(blk_sum(ss, sh) * (1.f/(float)(DM-1)));
    #pragma unroll
    for (int i = 0; i < 4; i++) {
        int c = threadIdx.x + i*256;
        float y = (v[i]-mean)*rstd;
        out[row*DM + c] = y;
        if (PL) splitw(y, oh, ol, row*DM + c);
    }
}

// ---------------- launch ----------------
extern "C" void kernel_launch(void* const* d_in, const int* in_sizes, int n_in,
                              void* d_out, int out_size) {
    const float* x  = (const float*)d_in[0];
    const float* Wq = (const float*)d_in[1];
    const float* Wk = (const float*)d_in[2];
    const float* Wv = (const float*)d_in[3];
    const float* Wo = (const float*)d_in[4];
    const float* W1 = (const float*)d_in[5];
    const float* b1 = (const float*)d_in[6];
    const float* W2 = (const float*)d_in[7];
    const float* b2 = (const float*)d_in[8];
    float* out = (float*)d_out;

    bf16 *WqkvTh,*WqkvTl,*WoTh,*WoTl,*W1Th,*W1Tl,*W2Th,*W2Tl,*xph,*xpl;
    bf16 *qh,*ql,*sch,*vth,*vtl,*obh,*obl,*o1h,*o1l,*h1h,*h1l;
    float *Zp,*Zr,*proj,*out1,*ff;
    cudaGetSymbolAddress((void**)&WqkvTh, g_WqkvT_h); cudaGetSymbolAddress((void**)&WqkvTl, g_WqkvT_l);
    cudaGetSymbolAddress((void**)&WoTh, g_WoT_h);     cudaGetSymbolAddress((void**)&WoTl, g_WoT_l);
    cudaGetSymbolAddress((void**)&W1Th, g_W1T_h);     cudaGetSymbolAddress((void**)&W1Tl, g_W1T_l);
    cudaGetSymbolAddress((void**)&W2Th, g_W2T_h);     cudaGetSymbolAddress((void**)&W2Tl, g_W2T_l);
    cudaGetSymbolAddress((void**)&xph, g_xp_h);       cudaGetSymbolAddress((void**)&xpl, g_xp_l);
    cudaGetSymbolAddress((void**)&qh, g_qkv_h);       cudaGetSymbolAddress((void**)&ql, g_qkv_l);
    cudaGetSymbolAddress((void**)&sch, g_sc_h);
    cudaGetSymbolAddress((void**)&vth, g_vt_h);       cudaGetSymbolAddress((void**)&vtl, g_vt_l);
    cudaGetSymbolAddress((void**)&obh, g_ob_h);       cudaGetSymbolAddress((void**)&obl, g_ob_l);
    cudaGetSymbolAddress((void**)&o1h, g_o1_h);       cudaGetSymbolAddress((void**)&o1l, g_o1_l);
    cudaGetSymbolAddress((void**)&h1h, g_h1_h);       cudaGetSymbolAddress((void**)&h1l, g_h1_l);
    cudaGetSymbolAddress((void**)&Zp, g_Zpart);       cudaGetSymbolAddress((void**)&Zr, g_Zr);
    cudaGetSymbolAddress((void**)&proj, g_proj);      cudaGetSymbolAddress((void**)&out1, g_out1);
    cudaGetSymbolAddress((void**)&ff, g_ff);

    const int SMF = 3*(2*128*40 + 2*128*40)*2 + 2048;   // 124928 (A2, BN=128)
    const int SMA = 3*(1*128*40 + 2*64*40)*2 + 2048;    // 63488 (attn-V)
    cudaFuncSetAttribute(mma_gemm<128,2,true>,  cudaFuncAttributeMaxDynamicSharedMemorySize, SMF);
    cudaFuncSetAttribute(mma_gemm<128,4,true>,  cudaFuncAttributeMaxDynamicSharedMemorySize, SMF);
    cudaFuncSetAttribute(mma_gemm<64,2,false>,  cudaFuncAttributeMaxDynamicSharedMemorySize, SMA);
    cudaFuncSetAttribute(mma_gemm<128,1,true>,  cudaFuncAttributeMaxDynamicSharedMemorySize, SMF);
    cudaFuncSetAttribute(mma_gemm<128,26,true>, cudaFuncAttributeMaxDynamicSharedMemorySize, SMF);
    cudaFuncSetAttribute(mma_gemm<128,9,true>,  cudaFuncAttributeMaxDynamicSharedMemorySize, SMF);

    const long long TT = (long long)TS*TS;

    // prep: planes for x + all weights
    split_x<<<(BT*DM)/256, 256>>>(x, xph, xpl);
    pack_wqkvT<<<(3*DM*DM)/256, 256>>>(Wq, Wk, Wv, WqkvTh, WqkvTl);
    transpose_split<<<dim3(DM/32, DM/32), dim3(32,8)>>>(Wo, WoTh, WoTl, DM, DM);
    transpose_split<<<dim3(FFD/32, DM/32), dim3(32,8)>>>(W1, W1Th, W1Tl, DM, FFD);
    transpose_split<<<dim3(DM/32, FFD/32), dim3(32,8)>>>(W2, W2Th, W2Tl, FFD, DM);

    // QKV = X @ WqkvT^T -> planes (4096x3072, K=1024)
    mma_gemm<128,2,true><<<dim3(3*DM/128, BT/128, 1), 256, SMF>>>(
        xph, xpl, WqkvTh, WqkvTl, nullptr, qh, ql, nullptr, nullptr,
        DM, DM, DM, 3*DM, 0,0, 0,0, 0,0, 1, 1.0f);

    // scores = exp(Q @ K^T / 8) hi-only + column sums; batched over (b,h)
    mma_gemm<128,4,true><<<dim3(TS/128, TS/128, NBH), 256, SMF>>>(
        qh, ql, qh + DM, ql + DM, nullptr, sch, nullptr, nullptr, Zp,
        HD, 3*DM, 3*DM, TS,
        (long long)TS*3*DM, HD, (long long)TS*3*DM, HD,
        (long long)NH*TT, TT, NH, 0.125f);

    zreduce<<<(NBH*TS)/256, 256>>>(Zp, Zr);
    vscale<<<dim3(TS/32, HD/32, NBH), dim3(32,8)>>>(qh, ql, Zr, vth, vtl);

    // O = scores_hi @ (V/Z)^T -> planes (per bh: 2048x64, K=2048)
    mma_gemm<64,2,false><<<dim3(1, TS/128, NBH), 256, SMA>>>(
        sch, nullptr, vth, vtl, nullptr, obh, obl, nullptr, nullptr,
        TS, TS, TS, DM,
        (long long)NH*TT, TT, (long long)NH*HD*TS, (long long)HD*TS,
        (long long)TS*DM, HD, NH, 1.0f);

    // proj = O @ WoT^T (fp32)
    mma_gemm<128,1,true><<<dim3(DM/128, BT/128, 1), 256, SMF>>>(
        obh, obl, WoTh, WoTl, proj, nullptr, nullptr, nullptr, nullptr,
        DM, DM, DM, DM, 0,0, 0,0, 0,0, 1, 1.0f);

    add_norm<true><<<BT, 256>>>(proj, x, out1, o1h, o1l);

    // h1 = relu(out1 @ W1T^T + b1) -> planes
    mma_gemm<128,26,true><<<dim3(FFD/128, BT/128, 1), 256, SMF>>>(
        o1h, o1l, W1Th, W1Tl, nullptr, h1h, h1l, b1, nullptr,
        DM, DM, DM, FFD, 0,0, 0,0, 0,0, 1, 1.0f);

    // ff = h1 @ W2T^T + b2 (fp32)
    mma_gemm<128,9,true><<<dim3(DM/128, BT/128, 1), 256, SMF>>>(
        h1h, h1l, W2Th, W2Tl, ff, nullptr, nullptr, b2, nullptr,
        FFD, FFD, FFD, DM, 0,0, 0,0, 0,0, 1, 1.0f);

    add_norm<false><<<BT, 256>>>(ff, out1, out, nullptr, nullptr);
}

// round 10
// speedup vs baseline: 3.3496x; 1.3735x over previous
#include <cuda_runtime.h>
#include <cuda_bf16.h>
#include <cstdint>
typedef __nv_bfloat16 bf16;

#define BATCH 2
#define TS 2048
#define DM 1024
#define NH 16
#define HD 64
#define FFD 4096
#define BT (BATCH*TS)
#define NBH (BATCH*NH)

// ---------------- scratch planes (no allocation) ----------------
__device__ __align__(16) bf16 g_WqkvT_h[(size_t)3*DM*DM];
__device__ __align__(16) bf16 g_WoT_h[(size_t)DM*DM];
__device__ __align__(16) bf16 g_W1T_h[(size_t)FFD*DM];
__device__ __align__(16) bf16 g_W1T_l[(size_t)FFD*DM];
__device__ __align__(16) bf16 g_W2T_h[(size_t)DM*FFD];
__device__ __align__(16) bf16 g_W2T_l[(size_t)DM*FFD];
__device__ __align__(16) bf16 g_xp_h[(size_t)BT*DM];
__device__ __align__(16) bf16 g_qkv_h[(size_t)BT*3*DM];
__device__ __align__(16) bf16 g_sc_h[(size_t)NBH*TS*TS];      // exp(QK/8), hi only
__device__ __align__(16) float g_Zpart[(size_t)NBH*16*TS];
__device__ __align__(16) float g_Zr[(size_t)NBH*TS];
__device__ __align__(16) bf16 g_vt_h[(size_t)NBH*HD*TS];
__device__ __align__(16) bf16 g_ob_h[(size_t)BT*DM];
__device__ __align__(16) float g_proj[(size_t)BT*DM];
__device__ __align__(16) float g_out1[(size_t)BT*DM];
__device__ __align__(16) bf16 g_o1_h[(size_t)BT*DM];
__device__ __align__(16) bf16 g_o1_l[(size_t)BT*DM];
__device__ __align__(16) bf16 g_h1_h[(size_t)BT*FFD];
__device__ __align__(16) bf16 g_h1_l[(size_t)BT*FFD];
__device__ __align__(16) float g_ff[(size_t)BT*DM];

// ---------------- helpers ----------------
__device__ __forceinline__ uint32_t smem_u32(const void* p) {
    uint32_t a;
    asm("{ .reg .u64 t; cvta.to.shared.u64 t, %1; cvt.u32.u64 %0, t; }" : "=r"(a) : "l"(p));
    return a;
}
__device__ __forceinline__ void ldsm4(uint32_t (&r)[4], uint32_t addr) {
    asm volatile("ldmatrix.sync.aligned.m8n8.x4.shared.b16 {%0,%1,%2,%3}, [%4];"
        : "=r"(r[0]), "=r"(r[1]), "=r"(r[2]), "=r"(r[3]) : "r"(addr));
}
__device__ __forceinline__ void mma16816(float (&d)[4], const uint32_t (&a)[4],
                                         const uint32_t* b) {
    asm volatile("mma.sync.aligned.m16n8k16.row.col.f32.bf16.bf16.f32 "
        "{%0,%1,%2,%3}, {%4,%5,%6,%7}, {%8,%9}, {%0,%1,%2,%3};"
        : "+f"(d[0]), "+f"(d[1]), "+f"(d[2]), "+f"(d[3])
        : "r"(a[0]), "r"(a[1]), "r"(a[2]), "r"(a[3]), "r"(b[0]), "r"(b[1]));
}
#define CP16(dst, src) asm volatile("cp.async.cg.shared.global [%0], [%1], 16;" :: "r"(dst), "l"(src) : "memory")
#define CPC()  asm volatile("cp.async.commit_group;" ::: "memory")
#define CPW1() asm volatile("cp.async.wait_group 1;" ::: "memory")
#define CPW0() asm volatile("cp.async.wait_group 0;" ::: "memory")

__device__ __forceinline__ uint32_t pack2(bf16 a, bf16 b) {
    __nv_bfloat162 t; t.x = a; t.y = b;
    return *reinterpret_cast<uint32_t*>(&t);
}
__device__ __forceinline__ void cvt2(float a, float b, uint32_t& hi, uint32_t& lo) {
    bf16 h0 = __float2bfloat16(a), h1 = __float2bfloat16(b);
    hi = pack2(h0, h1);
    lo = pack2(__float2bfloat16(a - __bfloat162float(h0)),
               __float2bfloat16(b - __bfloat162float(h1)));
}
__device__ __forceinline__ void splitw(float x, bf16* oh, bf16* ol, size_t i) {
    bf16 h = __float2bfloat16(x);
    oh[i] = h; ol[i] = __float2bfloat16(x - __bfloat162float(h));
}

// ---------------- plane GEMM: C = f(alpha * A @ B^T) ----------------
// A hi (+lo if A2) planes [M][K] (lda); B hi (+lo if B2) planes [N][K] (ldb).
// Terms: Ah*Bh (+Ah*Bl if B2) (+Al*Bh if A2).
// 3-stage cp.async ring, one __syncthreads per K-chunk, prefetch before compute.
// MODE bits: 1=fp32 out, 2=hi/lo plane out, 4=exp->hi plane+Zpart, 8=bias, 16=relu, 32=hi-only out
template<int BN, int MODE, bool A2, bool B2>
__global__ void __launch_bounds__(256)
mma_gemm(const bf16* __restrict__ Ah, const bf16* __restrict__ Al,
         const bf16* __restrict__ Bh, const bf16* __restrict__ Bl,
         float* __restrict__ Cf, bf16* __restrict__ Ch, bf16* __restrict__ Cl,
         const float* __restrict__ bias, float* __restrict__ Zpart,
         int K, int lda, int ldb, int ldc,
         long long sA1, long long sA2, long long sB1, long long sB2,
         long long sC1, long long sC2, int zInner, float alpha)
{
    constexpr int BM = 128, WC = 2, WN = BN/WC, NF = WN/8;
    constexpr int LDT = 40;                         // 80B rows: ldmatrix conflict-free
    constexpr int NPA = A2 ? 2 : 1, NPB = B2 ? 2 : 1;
    constexpr int APL = BM*LDT, BPL = BN*LDT;       // elems per plane
    constexpr int SSZ = NPA*APL + NPB*BPL;          // elems per stage
    constexpr int NST = 3;
    constexpr int NGA = NPA*BM*4/256, NGB = NPB*BN*4/256;

    extern __shared__ char dsm[];
    float* sZ = (float*)(dsm + (size_t)NST*SSZ*2);
    const uint32_t sbase = smem_u32(dsm);

    const int tid = threadIdx.x, wid = tid >> 5, lane = tid & 31;
    const int wr = wid & 3, wc = wid >> 2, g = lane >> 2, tig = lane & 3;
    const int z = blockIdx.z, z1 = z / zInner, z2 = z % zInner;
    const int row0 = blockIdx.y * BM, col0 = blockIdx.x * BN;
    const bf16* pAh = Ah + z1*sA1 + z2*sA2 + (size_t)row0*lda;
    const bf16* pAl = A2 ? (Al + z1*sA1 + z2*sA2 + (size_t)row0*lda) : nullptr;
    const bf16* pBh = Bh + z1*sB1 + z2*sB2 + (size_t)col0*ldb;
    const bf16* pBl = B2 ? (Bl + z1*sB1 + z2*sB2 + (size_t)col0*ldb) : nullptr;

    float acc[2][NF][4];
    #pragma unroll
    for (int mf = 0; mf < 2; mf++)
        #pragma unroll
        for (int nf = 0; nf < NF; nf++)
            #pragma unroll
            for (int q = 0; q < 4; q++) acc[mf][nf][q] = 0.f;

    const int NC = K >> 5;

    auto loadS = [&](int c, int buf) {
        const uint32_t sb = sbase + (uint32_t)buf*SSZ*2;
        const int k0 = c << 5;
        #pragma unroll
        for (int i = 0; i < NGA; i++) {
            int gi = tid + i*256;
            int p = gi >> 9, rem = gi & 511, r = rem >> 2, q = rem & 3;
            const bf16* src = (p ? pAl : pAh) + (size_t)r*lda + k0 + q*8;
            CP16(sb + (uint32_t)(p*APL + r*LDT + q*8)*2, src);
        }
        #pragma unroll
        for (int i = 0; i < NGB; i++) {
            int gi = tid + i*256;
            int p = gi / (BN*4), rem = gi % (BN*4), r = rem >> 2, q = rem & 3;
            const bf16* src = (p ? pBl : pBh) + (size_t)r*ldb + k0 + q*8;
            CP16(sb + (uint32_t)(NPA*APL + p*BPL + r*LDT + q*8)*2, src);
        }
        CPC();
    };

    auto comp = [&](int buf) {
        const uint32_t aB = sbase + (uint32_t)buf*SSZ*2;
        const uint32_t alB = aB + APL*2;
        const uint32_t bB = aB + NPA*APL*2, blB = bB + BPL*2;
        #pragma unroll
        for (int ks = 0; ks < 2; ks++) {
            uint32_t ah[2][4], al[2][4], bh[NF][2], bl[NF][2];
            #pragma unroll
            for (int mf = 0; mf < 2; mf++) {
                int row = wr*32 + mf*16 + (lane & 15);
                int kc  = ks*16 + ((lane >> 4) << 3);
                uint32_t off = (uint32_t)(row*LDT + kc)*2;
                ldsm4(ah[mf], aB + off);
                if (A2) ldsm4(al[mf], alB + off);
            }
            #pragma unroll
            for (int nq = 0; nq < NF/2; nq++) {
                int n  = wc*WN + nq*16 + (lane & 7) + ((lane >> 4) << 3);
                int kc = ks*16 + (((lane >> 3) & 1) << 3);
                uint32_t off = (uint32_t)(n*LDT + kc)*2, t[4];
                ldsm4(t, bB + off);
                bh[2*nq][0]=t[0]; bh[2*nq][1]=t[1]; bh[2*nq+1][0]=t[2]; bh[2*nq+1][1]=t[3];
                if (B2) {
                    ldsm4(t, blB + off);
                    bl[2*nq][0]=t[0]; bl[2*nq][1]=t[1]; bl[2*nq+1][0]=t[2]; bl[2*nq+1][1]=t[3];
                }
            }
            #pragma unroll
            for (int mf = 0; mf < 2; mf++)
                #pragma unroll
                for (int nf = 0; nf < NF; nf++) {
                    mma16816(acc[mf][nf], ah[mf], bh[nf]);
                    if (B2) mma16816(acc[mf][nf], ah[mf], bl[nf]);
                    if (A2) mma16816(acc[mf][nf], al[mf], bh[nf]);
                }
        }
    };

    loadS(0, 0);
    if (NC > 1) loadS(1, 1);
    int bufc = 0, bufl = 2;
    for (int c = 0; c < NC; c++) {
        if (c + 1 < NC) { CPW1(); } else { CPW0(); }
        __syncthreads();
        if (c + 2 < NC) loadS(c + 2, bufl);
        comp(bufc);
        bufc = (bufc == 2) ? 0 : bufc + 1;
        bufl = (bufl == 2) ? 0 : bufl + 1;
    }

    // ---- epilogue ----
    float* pCf = (MODE & 1) ? (Cf + z1*sC1 + z2*sC2) : nullptr;
    bf16* pCh = (MODE & 38) ? (Ch + z1*sC1 + z2*sC2) : nullptr;
    bf16* pCl = (MODE & 2) ? (Cl + z1*sC1 + z2*sC2) : nullptr;
    float cs[NF][2];
    if (MODE & 4)
        #pragma unroll
        for (int nf = 0; nf < NF; nf++) { cs[nf][0] = 0.f; cs[nf][1] = 0.f; }

    #pragma unroll
    for (int mf = 0; mf < 2; mf++) {
        int rg = row0 + wr*32 + mf*16 + g;
        #pragma unroll
        for (int nf = 0; nf < NF; nf++) {
            int col = col0 + wc*WN + nf*8 + tig*2;
            float v0 = acc[mf][nf][0], v1 = acc[mf][nf][1];
            float v2 = acc[mf][nf][2], v3 = acc[mf][nf][3];
            if (MODE & 8) {
                float b0 = __ldg(bias + col), b1 = __ldg(bias + col + 1);
                v0 += b0; v1 += b1; v2 += b0; v3 += b1;
            }
            if (MODE & 16) {
                v0 = fmaxf(v0, 0.f); v1 = fmaxf(v1, 0.f);
                v2 = fmaxf(v2, 0.f); v3 = fmaxf(v3, 0.f);
            }
            if (MODE & 4) {
                bf16 e0 = __float2bfloat16(__expf(v0*alpha));
                bf16 e1 = __float2bfloat16(__expf(v1*alpha));
                bf16 e2 = __float2bfloat16(__expf(v2*alpha));
                bf16 e3 = __float2bfloat16(__expf(v3*alpha));
                cs[nf][0] += __bfloat162float(e0) + __bfloat162float(e2);
                cs[nf][1] += __bfloat162float(e1) + __bfloat162float(e3);
                *reinterpret_cast<uint32_t*>(pCh + (size_t)rg*ldc + col)     = pack2(e0, e1);
                *reinterpret_cast<uint32_t*>(pCh + (size_t)(rg+8)*ldc + col) = pack2(e2, e3);
            } else if (MODE & 32) {
                *reinterpret_cast<uint32_t*>(pCh + (size_t)rg*ldc + col) =
                    pack2(__float2bfloat16(v0), __float2bfloat16(v1));
                *reinterpret_cast<uint32_t*>(pCh + (size_t)(rg+8)*ldc + col) =
                    pack2(__float2bfloat16(v2), __float2bfloat16(v3));
            } else if (MODE & 2) {
                uint32_t h, l;
                cvt2(v0, v1, h, l);
                *reinterpret_cast<uint32_t*>(pCh + (size_t)rg*ldc + col) = h;
                *reinterpret_cast<uint32_t*>(pCl + (size_t)rg*ldc + col) = l;
                cvt2(v2, v3, h, l);
                *reinterpret_cast<uint32_t*>(pCh + (size_t)(rg+8)*ldc + col) = h;
                *reinterpret_cast<uint32_t*>(pCl + (size_t)(rg+8)*ldc + col) = l;
            }
            if (MODE & 1) {
                float2 s01; s01.x = v0; s01.y = v1;
                float2 s23; s23.x = v2; s23.y = v3;
                *reinterpret_cast<float2*>(pCf + (size_t)rg*ldc + col) = s01;
                *reinterpret_cast<float2*>(pCf + (size_t)(rg+8)*ldc + col) = s23;
            }
        }
    }
    if (MODE & 4) {
        #pragma unroll
        for (int o = 4; o <= 16; o <<= 1)
            #pragma unroll
            for (int nf = 0; nf < NF; nf++) {
                cs[nf][0] += __shfl_xor_sync(0xffffffffu, cs[nf][0], o);
                cs[nf][1] += __shfl_xor_sync(0xffffffffu, cs[nf][1], o);
            }
        if (lane < 4) {
            #pragma unroll
            for (int nf = 0; nf < NF; nf++) {
                int lc = wc*WN + nf*8 + lane*2;
                sZ[wr*BN + lc]     = cs[nf][0];
                sZ[wr*BN + lc + 1] = cs[nf][1];
            }
        }
        __syncthreads();
        for (int c = tid; c < BN; c += 256) {
            float s = sZ[c] + sZ[BN + c] + sZ[2*BN + c] + sZ[3*BN + c];
            Zpart[((size_t)z*gridDim.y + blockIdx.y)*TS + col0 + c] = s;
        }
    }
}

// ---------------- prep / elementwise kernels ----------------
__global__ void split_x(const float* __restrict__ in, bf16* __restrict__ oh) {
    size_t i = (size_t)blockIdx.x*256 + threadIdx.x;
    oh[i] = __float2bfloat16(in[i]);
}
__global__ void pack_wqkvT(const float* __restrict__ Wq, const float* __restrict__ Wk,
                           const float* __restrict__ Wv, bf16* __restrict__ oh) {
    size_t idx = (size_t)blockIdx.x*256 + threadIdx.x;  // 3072*1024
    int n = (int)(idx >> 10), d = (int)(idx & 1023);
    const float* W = (n < DM) ? Wq : ((n < 2*DM) ? Wk : Wv);
    int nn = n & (DM-1), h = nn >> 6, kk = nn & 63;
    oh[idx] = __float2bfloat16(__ldg(&W[((size_t)h*DM + d)*HD + kk]));
}
// transpose fp32 [R][C] -> hi (+lo) planes [C][R]
template<bool LO>
__global__ void transpose_split(const float* __restrict__ in, bf16* __restrict__ oh,
                                bf16* __restrict__ ol, int R, int C) {
    __shared__ float t[32][33];
    int r0 = blockIdx.y*32, c0 = blockIdx.x*32;
    int tx = threadIdx.x, ty = threadIdx.y;
    #pragma unroll
    for (int i = 0; i < 32; i += 8)
        t[ty+i][tx] = in[(size_t)(r0+ty+i)*C + c0 + tx];
    __syncthreads();
    #pragma unroll
    for (int i = 0; i < 32; i += 8) {
        float x = t[tx][ty+i];
        size_t o = (size_t)(c0+ty+i)*R + r0 + tx;
        if (LO) splitw(x, oh, ol, o);
        else    oh[o] = __float2bfloat16(x);
    }
}
__global__ void zreduce(const float* __restrict__ Zpart, float* __restrict__ Zr) {
    int i = blockIdx.x*256 + threadIdx.x;
    int bh = i / TS, s = i % TS;
    float zv = 0.f;
    #pragma unroll
    for (int y = 0; y < 16; y++) zv += Zpart[((size_t)bh*16 + y)*TS + s];
    Zr[i] = 1.f / zv;
}
__global__ void vscale(const bf16* __restrict__ qh, const float* __restrict__ Zr,
                       bf16* __restrict__ oh) {
    __shared__ float t[32][33];
    int bh = blockIdx.z, b = bh >> 4, h = bh & 15;
    int s0 = blockIdx.x*32, v0 = blockIdx.y*32;
    int tx = threadIdx.x, ty = threadIdx.y;
    #pragma unroll
    for (int i = 0; i < 32; i += 8) {
        int s = s0 + ty + i, v = v0 + tx;
        size_t o = (size_t)(b*TS + s)*(3*DM) + 2*DM + h*HD + v;
        t[ty+i][tx] = __bfloat162float(qh[o]) * Zr[(size_t)bh*TS + s];
    }
    __syncthreads();
    #pragma unroll
    for (int i = 0; i < 32; i += 8) {
        int v = v0 + ty + i, s = s0 + tx;
        oh[((size_t)bh*HD + v)*TS + s] = __float2bfloat16(t[tx][ty+i]);
    }
}
__device__ __forceinline__ float blk_sum(float v, float* sh) {
    int lane = threadIdx.x & 31, warp = threadIdx.x >> 5;
    #pragma unroll
    for (int o = 16; o; o >>= 1) v += __shfl_xor_sync(0xffffffffu, v, o);
    if (lane == 0) sh[warp] = v;
    __syncthreads();
    if (warp == 0) {
        v = (lane < 8) ? sh[lane] : 0.f;
        #pragma unroll
        for (int o = 16; o; o >>= 1) v += __shfl_xor_sync(0xffffffffu, v, o);
        if (lane == 0) sh[0] = v;
    }
    __syncthreads();
    float r = sh[0];
    __syncthreads();
    return r;
}
template<bool PL>
__global__ void add_norm(const float* __restrict__ A, const float* __restrict__ B,
                         float* __restrict__ out, bf16* __restrict__ oh,
                         bf16* __restrict__ ol) {
    __shared__ float sh[32];
    size_t row = blockIdx.x;
    const float* pa = A + row*DM;
    const float* pb = B + row*DM;
    float v[4], s = 0.f;
    #pragma unroll
    for (int i = 0; i < 4; i++) {
        int c = threadIdx.x + i*256;
        v[i] = pa[c] + pb[c];
        s += v[i];
    }
    float mean = blk_sum(s, sh) * (1.f/(float)DM);
    float ss = 0.f;
    #pragma unroll
    for (int i = 0; i < 4; i++) { float d = v[i]-mean; ss += d*d; }
    float rstd = rsqrtf(blk_sum(ss, sh) * (1.f/(float)(DM-1)));
    #pragma unroll
    for (int i = 0; i < 4; i++) {
        int c = threadIdx.x + i*256;
        float y = (v[i]-mean)*rstd;
        out[row*DM + c] = y;
        if (PL) splitw(y, oh, ol, row*DM + c);
    }
}

// ---------------- launch ----------------
extern "C" void kernel_launch(void* const* d_in, const int* in_sizes, int n_in,
                              void* d_out, int out_size) {
    const float* x  = (const float*)d_in[0];
    const float* Wq = (const float*)d_in[1];
    const float* Wk = (const float*)d_in[2];
    const float* Wv = (const float*)d_in[3];
    const float* Wo = (const float*)d_in[4];
    const float* W1 = (const float*)d_in[5];
    const float* b1 = (const float*)d_in[6];
    const float* W2 = (const float*)d_in[7];
    const float* b2 = (const float*)d_in[8];
    float* out = (float*)d_out;

    bf16 *WqkvTh,*WoTh,*W1Th,*W1Tl,*W2Th,*W2Tl,*xph,*qh,*sch,*vth,*obh;
    bf16 *o1h,*o1l,*h1h,*h1l;
    float *Zp,*Zr,*proj,*out1,*ff;
    cudaGetSymbolAddress((void**)&WqkvTh, g_WqkvT_h);
    cudaGetSymbolAddress((void**)&WoTh, g_WoT_h);
    cudaGetSymbolAddress((void**)&W1Th, g_W1T_h); cudaGetSymbolAddress((void**)&W1Tl, g_W1T_l);
    cudaGetSymbolAddress((void**)&W2Th, g_W2T_h); cudaGetSymbolAddress((void**)&W2Tl, g_W2T_l);
    cudaGetSymbolAddress((void**)&xph, g_xp_h);
    cudaGetSymbolAddress((void**)&qh, g_qkv_h);
    cudaGetSymbolAddress((void**)&sch, g_sc_h);
    cudaGetSymbolAddress((void**)&vth, g_vt_h);
    cudaGetSymbolAddress((void**)&obh, g_ob_h);
    cudaGetSymbolAddress((void**)&o1h, g_o1_h);   cudaGetSymbolAddress((void**)&o1l, g_o1_l);
    cudaGetSymbolAddress((void**)&h1h, g_h1_h);   cudaGetSymbolAddress((void**)&h1l, g_h1_l);
    cudaGetSymbolAddress((void**)&Zp, g_Zpart);   cudaGetSymbolAddress((void**)&Zr, g_Zr);
    cudaGetSymbolAddress((void**)&proj, g_proj);  cudaGetSymbolAddress((void**)&out1, g_out1);
    cudaGetSymbolAddress((void**)&ff, g_ff);

    const int SM1 = 3*(128*40 + 128*40)*2 + 2048;       // 63488: 1-term BN=128
    const int SMA = 3*(128*40 + 64*40)*2 + 2048;        // 48128: 1-term BN=64
    const int SM3 = 3*(2*128*40 + 2*128*40)*2 + 2048;   // 124928: 3-term BN=128
    cudaFuncSetAttribute(mma_gemm<128,32,false,false>, cudaFuncAttributeMaxDynamicSharedMemorySize, SM1);
    cudaFuncSetAttribute(mma_gemm<128,4,false,false>,  cudaFuncAttributeMaxDynamicSharedMemorySize, SM1);
    cudaFuncSetAttribute(mma_gemm<64,32,false,false>,  cudaFuncAttributeMaxDynamicSharedMemorySize, SMA);
    cudaFuncSetAttribute(mma_gemm<128,1,false,false>,  cudaFuncAttributeMaxDynamicSharedMemorySize, SM1);
    cudaFuncSetAttribute(mma_gemm<128,26,true,true>,   cudaFuncAttributeMaxDynamicSharedMemorySize, SM3);
    cudaFuncSetAttribute(mma_gemm<128,9,true,true>,    cudaFuncAttributeMaxDynamicSharedMemorySize, SM3);

    const long long TT = (long long)TS*TS;

    // prep
    split_x<<<(BT*DM)/256, 256>>>(x, xph);
    pack_wqkvT<<<(3*DM*DM)/256, 256>>>(Wq, Wk, Wv, WqkvTh);
    transpose_split<false><<<dim3(DM/32, DM/32), dim3(32,8)>>>(Wo, WoTh, nullptr, DM, DM);
    transpose_split<true><<<dim3(FFD/32, DM/32), dim3(32,8)>>>(W1, W1Th, W1Tl, DM, FFD);
    transpose_split<true><<<dim3(DM/32, FFD/32), dim3(32,8)>>>(W2, W2Th, W2Tl, FFD, DM);

    // QKV = X @ WqkvT^T -> hi plane (1-term; attention path damped ~100x)
    mma_gemm<128,32,false,false><<<dim3(3*DM/128, BT/128, 1), 256, SM1>>>(
        xph, nullptr, WqkvTh, nullptr, nullptr, qh, nullptr, nullptr, nullptr,
        DM, DM, DM, 3*DM, 0,0, 0,0, 0,0, 1, 1.0f);

    // scores = exp(Q @ K^T / 8) hi plane + column sums (1-term)
    mma_gemm<128,4,false,false><<<dim3(TS/128, TS/128, NBH), 256, SM1>>>(
        qh, nullptr, qh + DM, nullptr, nullptr, sch, nullptr, nullptr, Zp,
        HD, 3*DM, 3*DM, TS,
        (long long)TS*3*DM, HD, (long long)TS*3*DM, HD,
        (long long)NH*TT, TT, NH, 0.125f);

    zreduce<<<(NBH*TS)/256, 256>>>(Zp, Zr);
    vscale<<<dim3(TS/32, HD/32, NBH), dim3(32,8)>>>(qh, Zr, vth);

    // O = scores_hi @ (V/Z)^T -> hi plane (1-term)
    mma_gemm<64,32,false,false><<<dim3(1, TS/128, NBH), 256, SMA>>>(
        sch, nullptr, vth, nullptr, nullptr, obh, nullptr, nullptr, nullptr,
        TS, TS, TS, DM,
        (long long)NH*TT, TT, (long long)NH*HD*TS, (long long)HD*TS,
        (long long)TS*DM, HD, NH, 1.0f);

    // proj = O @ WoT^T (fp32, 1-term)
    mma_gemm<128,1,false,false><<<dim3(DM/128, BT/128, 1), 256, SM1>>>(
        obh, nullptr, WoTh, nullptr, proj, nullptr, nullptr, nullptr, nullptr,
        DM, DM, DM, DM, 0,0, 0,0, 0,0, 1, 1.0f);

    add_norm<true><<<BT, 256>>>(proj, x, out1, o1h, o1l);

    // h1 = relu(out1 @ W1T^T + b1) -> hi/lo planes (3-term: sensitive path)
    mma_gemm<128,26,true,true><<<dim3(FFD/128, BT/128, 1), 256, SM3>>>(
        o1h, o1l, W1Th, W1Tl, nullptr, h1h, h1l, b1, nullptr,
        DM, DM, DM, FFD, 0,0, 0,0, 0,0, 1, 1.0f);

    // ff = h1 @ W2T^T + b2 (fp32, 3-term)
    mma_gemm<128,9,true,true><<<dim3(DM/128, BT/128, 1), 256, SM3>>>(
        h1h, h1l, W2Th, W2Tl, ff, nullptr, nullptr, b2, nullptr,
        FFD, FFD, FFD, DM, 0,0, 0,0, 0,0, 1, 1.0f);

    add_norm<false><<<BT, 256>>>(ff, out1, out, nullptr, nullptr);
}

// round 11
// speedup vs baseline: 5.6485x; 1.6863x over previous
#include <cuda_runtime.h>
#include <cuda_fp16.h>
#include <cstdint>
typedef __half f16;

#define BATCH 2
#define TS 2048
#define DM 1024
#define NH 16
#define HD 64
#define FFD 4096
#define BT (BATCH*TS)
#define NBH (BATCH*NH)

// ---------------- scratch planes (fp16; no allocation) ----------------
__device__ __align__(16) f16 g_WqkvT[(size_t)3*DM*DM];
__device__ __align__(16) f16 g_WoT[(size_t)DM*DM];
__device__ __align__(16) f16 g_W1T[(size_t)FFD*DM];
__device__ __align__(16) f16 g_W2T[(size_t)DM*FFD];
__device__ __align__(16) f16 g_xp[(size_t)BT*DM];
__device__ __align__(16) f16 g_qkv[(size_t)BT*3*DM];
__device__ __align__(16) f16 g_sc[(size_t)NBH*TS*TS];       // exp(QK/8)
__device__ __align__(16) float g_Zpart[(size_t)NBH*16*TS];
__device__ __align__(16) float g_Zr[(size_t)NBH*TS];
__device__ __align__(16) f16 g_vt[(size_t)NBH*HD*TS];
__device__ __align__(16) f16 g_ob[(size_t)BT*DM];
__device__ __align__(16) float g_proj[(size_t)BT*DM];
__device__ __align__(16) float g_out1[(size_t)BT*DM];
__device__ __align__(16) f16 g_o1[(size_t)BT*DM];
__device__ __align__(16) f16 g_h1[(size_t)BT*FFD];
__device__ __align__(16) float g_ff[(size_t)BT*DM];

// ---------------- helpers ----------------
__device__ __forceinline__ uint32_t smem_u32(const void* p) {
    uint32_t a;
    asm("{ .reg .u64 t; cvta.to.shared.u64 t, %1; cvt.u32.u64 %0, t; }" : "=r"(a) : "l"(p));
    return a;
}
__device__ __forceinline__ void ldsm4(uint32_t (&r)[4], uint32_t addr) {
    asm volatile("ldmatrix.sync.aligned.m8n8.x4.shared.b16 {%0,%1,%2,%3}, [%4];"
        : "=r"(r[0]), "=r"(r[1]), "=r"(r[2]), "=r"(r[3]) : "r"(addr));
}
__device__ __forceinline__ void mma16816(float (&d)[4], const uint32_t (&a)[4],
                                         const uint32_t* b) {
    asm volatile("mma.sync.aligned.m16n8k16.row.col.f32.f16.f16.f32 "
        "{%0,%1,%2,%3}, {%4,%5,%6,%7}, {%8,%9}, {%0,%1,%2,%3};"
        : "+f"(d[0]), "+f"(d[1]), "+f"(d[2]), "+f"(d[3])
        : "r"(a[0]), "r"(a[1]), "r"(a[2]), "r"(a[3]), "r"(b[0]), "r"(b[1]));
}
#define CP16(dst, src) asm volatile("cp.async.cg.shared.global [%0], [%1], 16;" :: "r"(dst), "l"(src) : "memory")
#define CPC()  asm volatile("cp.async.commit_group;" ::: "memory")
#define CPW1() asm volatile("cp.async.wait_group 1;" ::: "memory")
#define CPW0() asm volatile("cp.async.wait_group 0;" ::: "memory")

__device__ __forceinline__ uint32_t pack2(f16 a, f16 b) {
    __half2 t; t.x = a; t.y = b;
    return *reinterpret_cast<uint32_t*>(&t);
}

// ---------------- fp16 GEMM: C = f(alpha * A @ B^T) ----------------
// A [M][K] (lda), B [N][K] (ldb), both fp16. 3-stage cp.async ring,
// one __syncthreads per K-chunk, prefetch before compute.
// MODE bits: 1=fp32 out, 4=exp->f16 plane + Zpart, 8=bias, 16=relu, 32=f16 out
template<int BN, int MODE>
__global__ void __launch_bounds__(256)
mma_gemm(const f16* __restrict__ A, const f16* __restrict__ B,
         float* __restrict__ Cf, f16* __restrict__ Ch,
         const float* __restrict__ bias, float* __restrict__ Zpart,
         int K, int lda, int ldb, int ldc,
         long long sA1, long long sA2, long long sB1, long long sB2,
         long long sC1, long long sC2, int zInner, float alpha)
{
    constexpr int BM = 128, WC = 2, WN = BN/WC, NF = WN/8;
    constexpr int LDT = 40;                       // 80B rows: ldmatrix conflict-free
    constexpr int APL = BM*LDT, BPL = BN*LDT;
    constexpr int SSZ = APL + BPL;
    constexpr int NST = 3;
    constexpr int NGA = BM*4/256, NGB = BN*4/256;

    extern __shared__ char dsm[];
    float* sZ = (float*)(dsm + (size_t)NST*SSZ*2);
    const uint32_t sbase = smem_u32(dsm);

    const int tid = threadIdx.x, wid = tid >> 5, lane = tid & 31;
    const int wr = wid & 3, wc = wid >> 2, g = lane >> 2, tig = lane & 3;
    const int z = blockIdx.z, z1 = z / zInner, z2 = z % zInner;
    const int row0 = blockIdx.y * BM, col0 = blockIdx.x * BN;
    const f16* pA = A + z1*sA1 + z2*sA2 + (size_t)row0*lda;
    const f16* pB = B + z1*sB1 + z2*sB2 + (size_t)col0*ldb;

    float acc[2][NF][4];
    #pragma unroll
    for (int mf = 0; mf < 2; mf++)
        #pragma unroll
        for (int nf = 0; nf < NF; nf++)
            #pragma unroll
            for (int q = 0; q < 4; q++) acc[mf][nf][q] = 0.f;

    const int NC = K >> 5;

    auto loadS = [&](int c, int buf) {
        const uint32_t sb = sbase + (uint32_t)buf*SSZ*2;
        const int k0 = c << 5;
        #pragma unroll
        for (int i = 0; i < NGA; i++) {
            int gi = tid + i*256;
            int r = gi >> 2, q = gi & 3;
            CP16(sb + (uint32_t)(r*LDT + q*8)*2, pA + (size_t)r*lda + k0 + q*8);
        }
        #pragma unroll
        for (int i = 0; i < NGB; i++) {
            int gi = tid + i*256;
            int r = gi >> 2, q = gi & 3;
            CP16(sb + (uint32_t)(APL + r*LDT + q*8)*2, pB + (size_t)r*ldb + k0 + q*8);
        }
        CPC();
    };

    auto comp = [&](int buf) {
        const uint32_t aB = sbase + (uint32_t)buf*SSZ*2;
        const uint32_t bB = aB + APL*2;
        #pragma unroll
        for (int ks = 0; ks < 2; ks++) {
            uint32_t ah[2][4], bh[NF][2];
            #pragma unroll
            for (int mf = 0; mf < 2; mf++) {
                int row = wr*32 + mf*16 + (lane & 15);
                int kc  = ks*16 + ((lane >> 4) << 3);
                ldsm4(ah[mf], aB + (uint32_t)(row*LDT + kc)*2);
            }
            #pragma unroll
            for (int nq = 0; nq < NF/2; nq++) {
                int n  = wc*WN + nq*16 + (lane & 7) + ((lane >> 4) << 3);
                int kc = ks*16 + (((lane >> 3) & 1) << 3);
                uint32_t t[4];
                ldsm4(t, bB + (uint32_t)(n*LDT + kc)*2);
                bh[2*nq][0]=t[0]; bh[2*nq][1]=t[1]; bh[2*nq+1][0]=t[2]; bh[2*nq+1][1]=t[3];
            }
            #pragma unroll
            for (int mf = 0; mf < 2; mf++)
                #pragma unroll
                for (int nf = 0; nf < NF; nf++)
                    mma16816(acc[mf][nf], ah[mf], bh[nf]);
        }
    };

    loadS(0, 0);
    if (NC > 1) loadS(1, 1);
    int bufc = 0, bufl = 2;
    for (int c = 0; c < NC; c++) {
        if (c + 1 < NC) { CPW1(); } else { CPW0(); }
        __syncthreads();
        if (c + 2 < NC) loadS(c + 2, bufl);
        comp(bufc);
        bufc = (bufc == 2) ? 0 : bufc + 1;
        bufl = (bufl == 2) ? 0 : bufl + 1;
    }

    // ---- epilogue ----
    float* pCf = (MODE & 1) ? (Cf + z1*sC1 + z2*sC2) : nullptr;
    f16* pCh = (MODE & 36) ? (Ch + z1*sC1 + z2*sC2) : nullptr;
    float cs[NF][2];
    if (MODE & 4)
        #pragma unroll
        for (int nf = 0; nf < NF; nf++) { cs[nf][0] = 0.f; cs[nf][1] = 0.f; }

    #pragma unroll
    for (int mf = 0; mf < 2; mf++) {
        int rg = row0 + wr*32 + mf*16 + g;
        #pragma unroll
        for (int nf = 0; nf < NF; nf++) {
            int col = col0 + wc*WN + nf*8 + tig*2;
            float v0 = acc[mf][nf][0], v1 = acc[mf][nf][1];
            float v2 = acc[mf][nf][2], v3 = acc[mf][nf][3];
            if (MODE & 8) {
                float b0 = __ldg(bias + col), b1 = __ldg(bias + col + 1);
                v0 += b0; v1 += b1; v2 += b0; v3 += b1;
            }
            if (MODE & 16) {
                v0 = fmaxf(v0, 0.f); v1 = fmaxf(v1, 0.f);
                v2 = fmaxf(v2, 0.f); v3 = fmaxf(v3, 0.f);
            }
            if (MODE & 4) {
                f16 e0 = __float2half(__expf(v0*alpha));
                f16 e1 = __float2half(__expf(v1*alpha));
                f16 e2 = __float2half(__expf(v2*alpha));
                f16 e3 = __float2half(__expf(v3*alpha));
                cs[nf][0] += __half2float(e0) + __half2float(e2);
                cs[nf][1] += __half2float(e1) + __half2float(e3);
                *reinterpret_cast<uint32_t*>(pCh + (size_t)rg*ldc + col)     = pack2(e0, e1);
                *reinterpret_cast<uint32_t*>(pCh + (size_t)(rg+8)*ldc + col) = pack2(e2, e3);
            } else if (MODE & 32) {
                *reinterpret_cast<uint32_t*>(pCh + (size_t)rg*ldc + col) =
                    pack2(__float2half(v0), __float2half(v1));
                *reinterpret_cast<uint32_t*>(pCh + (size_t)(rg+8)*ldc + col) =
                    pack2(__float2half(v2), __float2half(v3));
            }
            if (MODE & 1) {
                float2 s01; s01.x = v0; s01.y = v1;
                float2 s23; s23.x = v2; s23.y = v3;
                *reinterpret_cast<float2*>(pCf + (size_t)rg*ldc + col) = s01;
                *reinterpret_cast<float2*>(pCf + (size_t)(rg+8)*ldc + col) = s23;
            }
        }
    }
    if (MODE & 4) {
        #pragma unroll
        for (int o = 4; o <= 16; o <<= 1)
            #pragma unroll
            for (int nf = 0; nf < NF; nf++) {
                cs[nf][0] += __shfl_xor_sync(0xffffffffu, cs[nf][0], o);
                cs[nf][1] += __shfl_xor_sync(0xffffffffu, cs[nf][1], o);
            }
        if (lane < 4) {
            #pragma unroll
            for (int nf = 0; nf < NF; nf++) {
                int lc = wc*WN + nf*8 + lane*2;
                sZ[wr*BN + lc]     = cs[nf][0];
                sZ[wr*BN + lc + 1] = cs[nf][1];
            }
        }
        __syncthreads();
        for (int c = tid; c < BN; c += 256) {
            float s = sZ[c] + sZ[BN + c] + sZ[2*BN + c] + sZ[3*BN + c];
            Zpart[((size_t)z*gridDim.y + blockIdx.y)*TS + col0 + c] = s;
        }
    }
}

// ---------------- prep / elementwise kernels ----------------
__global__ void split_x(const float* __restrict__ in, f16* __restrict__ o) {
    size_t i = (size_t)blockIdx.x*256 + threadIdx.x;
    o[i] = __float2half(in[i]);
}
__global__ void pack_wqkvT(const float* __restrict__ Wq, const float* __restrict__ Wk,
                           const float* __restrict__ Wv, f16* __restrict__ o) {
    size_t idx = (size_t)blockIdx.x*256 + threadIdx.x;  // 3072*1024
    int n = (int)(idx >> 10), d = (int)(idx & 1023);
    const float* W = (n < DM) ? Wq : ((n < 2*DM) ? Wk : Wv);
    int nn = n & (DM-1), h = nn >> 6, kk = nn & 63;
    o[idx] = __float2half(__ldg(&W[((size_t)h*DM + d)*HD + kk]));
}
__global__ void transpose_h(const float* __restrict__ in, f16* __restrict__ o,
                            int R, int C) {
    __shared__ float t[32][33];
    int r0 = blockIdx.y*32, c0 = blockIdx.x*32;
    int tx = threadIdx.x, ty = threadIdx.y;
    #pragma unroll
    for (int i = 0; i < 32; i += 8)
        t[ty+i][tx] = in[(size_t)(r0+ty+i)*C + c0 + tx];
    __syncthreads();
    #pragma unroll
    for (int i = 0; i < 32; i += 8)
        o[(size_t)(c0+ty+i)*R + r0 + tx] = __float2half(t[tx][ty+i]);
}
__global__ void zreduce(const float* __restrict__ Zpart, float* __restrict__ Zr) {
    int i = blockIdx.x*256 + threadIdx.x;
    int bh = i / TS, s = i % TS;
    float zv = 0.f;
    #pragma unroll
    for (int y = 0; y < 16; y++) zv += Zpart[((size_t)bh*16 + y)*TS + s];
    Zr[i] = 1.f / zv;
}
__global__ void vscale(const f16* __restrict__ q, const float* __restrict__ Zr,
                       f16* __restrict__ o) {
    __shared__ float t[32][33];
    int bh = blockIdx.z, b = bh >> 4, h = bh & 15;
    int s0 = blockIdx.x*32, v0 = blockIdx.y*32;
    int tx = threadIdx.x, ty = threadIdx.y;
    #pragma unroll
    for (int i = 0; i < 32; i += 8) {
        int s = s0 + ty + i, v = v0 + tx;
        size_t off = (size_t)(b*TS + s)*(3*DM) + 2*DM + h*HD + v;
        t[ty+i][tx] = __half2float(q[off]) * Zr[(size_t)bh*TS + s];
    }
    __syncthreads();
    #pragma unroll
    for (int i = 0; i < 32; i += 8) {
        int v = v0 + ty + i, s = s0 + tx;
        o[((size_t)bh*HD + v)*TS + s] = __float2half(t[tx][ty+i]);
    }
}
__device__ __forceinline__ float blk_sum(float v, float* sh) {
    int lane = threadIdx.x & 31, warp = threadIdx.x >> 5;
    #pragma unroll
    for (int o = 16; o; o >>= 1) v += __shfl_xor_sync(0xffffffffu, v, o);
    if (lane == 0) sh[warp] = v;
    __syncthreads();
    if (warp == 0) {
        v = (lane < 8) ? sh[lane] : 0.f;
        #pragma unroll
        for (int o = 16; o; o >>= 1) v += __shfl_xor_sync(0xffffffffu, v, o);
        if (lane == 0) sh[0] = v;
    }
    __syncthreads();
    float r = sh[0];
    __syncthreads();
    return r;
}
template<bool PL>
__global__ void add_norm(const float* __restrict__ A, const float* __restrict__ B,
                         float* __restrict__ out, f16* __restrict__ oh) {
    __shared__ float sh[32];
    size_t row = blockIdx.x;
    const float* pa = A + row*DM;
    const float* pb = B + row*DM;
    float v[4], s = 0.f;
    #pragma unroll
    for (int i = 0; i < 4; i++) {
        int c = threadIdx.x + i*256;
        v[i] = pa[c] + pb[c];
        s += v[i];
    }
    float mean = blk_sum(s, sh) * (1.f/(float)DM);
    float ss = 0.f;
    #pragma unroll
    for (int i = 0; i < 4; i++) { float d = v[i]-mean; ss += d*d; }
    float rstd = rsqrtf(blk_sum(ss, sh) * (1.f/(float)(DM-1)));
    #pragma unroll
    for (int i = 0; i < 4; i++) {
        int c = threadIdx.x + i*256;
        float y = (v[i]-mean)*rstd;
        out[row*DM + c] = y;
        if (PL) oh[row*DM + c] = __float2half(y);
    }
}

// ---------------- launch ----------------
extern "C" void kernel_launch(void* const* d_in, const int* in_sizes, int n_in,
                              void* d_out, int out_size) {
    const float* x  = (const float*)d_in[0];
    const float* Wq = (const float*)d_in[1];
    const float* Wk = (const float*)d_in[2];
    const float* Wv = (const float*)d_in[3];
    const float* Wo = (const float*)d_in[4];
    const float* W1 = (const float*)d_in[5];
    const float* b1 = (const float*)d_in[6];
    const float* W2 = (const float*)d_in[7];
    const float* b2 = (const float*)d_in[8];
    float* out = (float*)d_out;

    f16 *WqkvT,*WoT,*W1T,*W2T,*xp,*q,*sc,*vt,*ob,*o1,*h1;
    float *Zp,*Zr,*proj,*out1,*ff;
    cudaGetSymbolAddress((void**)&WqkvT, g_WqkvT);
    cudaGetSymbolAddress((void**)&WoT, g_WoT);
    cudaGetSymbolAddress((void**)&W1T, g_W1T);
    cudaGetSymbolAddress((void**)&W2T, g_W2T);
    cudaGetSymbolAddress((void**)&xp, g_xp);
    cudaGetSymbolAddress((void**)&q, g_qkv);
    cudaGetSymbolAddress((void**)&sc, g_sc);
    cudaGetSymbolAddress((void**)&vt, g_vt);
    cudaGetSymbolAddress((void**)&ob, g_ob);
    cudaGetSymbolAddress((void**)&o1, g_o1);
    cudaGetSymbolAddress((void**)&h1, g_h1);
    cudaGetSymbolAddress((void**)&Zp, g_Zpart);   cudaGetSymbolAddress((void**)&Zr, g_Zr);
    cudaGetSymbolAddress((void**)&proj, g_proj);  cudaGetSymbolAddress((void**)&out1, g_out1);
    cudaGetSymbolAddress((void**)&ff, g_ff);

    const int SM1 = 3*(128*40 + 128*40)*2 + 2048;   // 63488: BN=128
    const int SMA = 3*(128*40 + 64*40)*2 + 2048;    // 48128: BN=64
    cudaFuncSetAttribute(mma_gemm<128,32>, cudaFuncAttributeMaxDynamicSharedMemorySize, SM1);
    cudaFuncSetAttribute(mma_gemm<128,4>,  cudaFuncAttributeMaxDynamicSharedMemorySize, SM1);
    cudaFuncSetAttribute(mma_gemm<64,32>,  cudaFuncAttributeMaxDynamicSharedMemorySize, SMA);
    cudaFuncSetAttribute(mma_gemm<128,1>,  cudaFuncAttributeMaxDynamicSharedMemorySize, SM1);
    cudaFuncSetAttribute(mma_gemm<128,56>, cudaFuncAttributeMaxDynamicSharedMemorySize, SM1);
    cudaFuncSetAttribute(mma_gemm<128,9>,  cudaFuncAttributeMaxDynamicSharedMemorySize, SM1);

    const long long TT = (long long)TS*TS;

    // prep (all fp16 single-plane)
    split_x<<<(BT*DM)/256, 256>>>(x, xp);
    pack_wqkvT<<<(3*DM*DM)/256, 256>>>(Wq, Wk, Wv, WqkvT);
    transpose_h<<<dim3(DM/32, DM/32), dim3(32,8)>>>(Wo, WoT, DM, DM);
    transpose_h<<<dim3(FFD/32, DM/32), dim3(32,8)>>>(W1, W1T, DM, FFD);
    transpose_h<<<dim3(DM/32, FFD/32), dim3(32,8)>>>(W2, W2T, FFD, DM);

    // QKV = X @ WqkvT^T -> f16 (4096x3072, K=1024)
    mma_gemm<128,32><<<dim3(3*DM/128, BT/128, 1), 256, SM1>>>(
        xp, WqkvT, nullptr, q, nullptr, nullptr,
        DM, DM, DM, 3*DM, 0,0, 0,0, 0,0, 1, 1.0f);

    // scores = exp(Q @ K^T / 8) f16 + column sums; batched over (b,h)
    mma_gemm<128,4><<<dim3(TS/128, TS/128, NBH), 256, SM1>>>(
        q, q + DM, nullptr, sc, nullptr, Zp,
        HD, 3*DM, 3*DM, TS,
        (long long)TS*3*DM, HD, (long long)TS*3*DM, HD,
        (long long)NH*TT, TT, NH, 0.125f);

    zreduce<<<(NBH*TS)/256, 256>>>(Zp, Zr);
    vscale<<<dim3(TS/32, HD/32, NBH), dim3(32,8)>>>(q, Zr, vt);

    // O = scores @ (V/Z)^T -> f16 (per bh: 2048x64, K=2048)
    mma_gemm<64,32><<<dim3(1, TS/128, NBH), 256, SMA>>>(
        sc, vt, nullptr, ob, nullptr, nullptr,
        TS, TS, TS, DM,
        (long long)NH*TT, TT, (long long)NH*HD*TS, (long long)HD*TS,
        (long long)TS*DM, HD, NH, 1.0f);

    // proj = O @ WoT^T (fp32 out)
    mma_gemm<128,1><<<dim3(DM/128, BT/128, 1), 256, SM1>>>(
        ob, WoT, proj, nullptr, nullptr, nullptr,
        DM, DM, DM, DM, 0,0, 0,0, 0,0, 1, 1.0f);

    add_norm<true><<<BT, 256>>>(proj, x, out1, o1);

    // h1 = relu(out1 @ W1T^T + b1) -> f16
    mma_gemm<128,56><<<dim3(FFD/128, BT/128, 1), 256, SM1>>>(
        o1, W1T, nullptr, h1, b1, nullptr,
        DM, DM, DM, FFD, 0,0, 0,0, 0,0, 1, 1.0f);

    // ff = h1 @ W2T^T + b2 (fp32 out)
    mma_gemm<128,9><<<dim3(DM/128, BT/128, 1), 256, SM1>>>(
        h1, W2T, ff, nullptr, b2, nullptr,
        FFD, FFD, FFD, DM, 0,0, 0,0, 0,0, 1, 1.0f);

    add_norm<false><<<BT, 256>>>(ff, out1, out, nullptr);
}